// round 13
// baseline (speedup 1.0000x reference)
#include <cuda_runtime.h>
#include <cuda_bf16.h>
#include <math.h>

#define BATCH 8
#define SS 1048576              // 128*128*64
#define NTOT (BATCH * SS)       // 8388608 per component
#define ALP 131072              // A-limb plane stride (B*128*128 max)
#define UTP NTOT                // big limb plane stride

// ---------------- scratch (device globals; no allocation) ----------------
__device__ float g_s_re[NTOT];
__device__ float g_s_im[NTOT];
__device__ float g_u_re[NTOT];
__device__ float g_u_im[NTOT];
__device__ float g_l_re[NTOT];
__device__ float g_l_im[NTOT];
__device__ float g_p_re[4194304];
__device__ float g_p_im[4194304];
__device__ float g_m_re[131072];
__device__ float g_m_im[131072];
__device__ __nv_bfloat16 g_abf[4 * ALP];   // A limbs: rhi,rlo,ihi,ilo
__device__ __nv_bfloat16 g_utbf[4 * UTP];  // U^T limbs (B,rest,d)
__device__ __nv_bfloat16 g_ubf[4 * UTP];   // U  limbs (B,d,rest)
__device__ __nv_bfloat16 g_lbf[4 * UTP];   // L  limbs (B,d,rest)

typedef unsigned long long u64;

// ================= limb conversion kernels ================================
__global__ void conv_limbs_A(const float* __restrict__ re, const float* __restrict__ im,
                             __nv_bfloat16* __restrict__ out, int n)
{
    int i = blockIdx.x * 256 + threadIdx.x;
    if (i >= n) return;
    float x = re[i];
    __nv_bfloat16 h = __float2bfloat16(x);
    out[0 * ALP + i] = h;
    out[1 * ALP + i] = __float2bfloat16(x - __bfloat162float(h));
    float y = im[i];
    __nv_bfloat16 ih = __float2bfloat16(y);
    out[2 * ALP + i] = ih;
    out[3 * ALP + i] = __float2bfloat16(y - __bfloat162float(ih));
}

// U (B,d,rest) fp32 -> UT limbs (B,rest,d) AND U limbs (B,d,rest)
__global__ void conv_ut(const float* __restrict__ ure, const float* __restrict__ uim,
                        __nv_bfloat16* __restrict__ outT, __nv_bfloat16* __restrict__ outU,
                        int d, int rest)
{
    __shared__ float tr[32][33], ti[32][33];
    const int b  = blockIdx.z;
    const int k0 = blockIdx.y * 32;       // d index
    const int n0 = blockIdx.x * 32;       // rest index
    const size_t ib = (size_t)b * d * rest;
    const size_t ob = (size_t)b * rest * d;
    const int x = threadIdx.x, y = threadIdx.y;   // 32 x 8
#pragma unroll
    for (int i = y; i < 32; i += 8) {
        size_t si = ib + (size_t)(k0 + i) * rest + n0 + x;
        float xr = ure[si], xi = uim[si];
        tr[i][x] = xr; ti[i][x] = xi;
        __nv_bfloat16 rh = __float2bfloat16(xr);
        __nv_bfloat16 ihh = __float2bfloat16(xi);
        outU[0 * (size_t)UTP + si] = rh;
        outU[1 * (size_t)UTP + si] = __float2bfloat16(xr - __bfloat162float(rh));
        outU[2 * (size_t)UTP + si] = ihh;
        outU[3 * (size_t)UTP + si] = __float2bfloat16(xi - __bfloat162float(ihh));
    }
    __syncthreads();
#pragma unroll
    for (int i = y; i < 32; i += 8) {
        size_t o = ob + (size_t)(n0 + i) * d + k0 + x;
        float xr = tr[x][i], xi = ti[x][i];
        __nv_bfloat16 rh = __float2bfloat16(xr);
        __nv_bfloat16 ihh = __float2bfloat16(xi);
        outT[0 * (size_t)UTP + o] = rh;
        outT[1 * (size_t)UTP + o] = __float2bfloat16(xr - __bfloat162float(rh));
        outT[2 * (size_t)UTP + o] = ihh;
        outT[3 * (size_t)UTP + o] = __float2bfloat16(xi - __bfloat162float(ihh));
    }
}

// ================= mma.sync helpers =======================================
__device__ __forceinline__ unsigned smem_u32(const void* p) {
    unsigned a;
    asm("{ .reg .u64 t; cvta.to.shared.u64 t, %1; cvt.u32.u64 %0, t; }"
        : "=r"(a) : "l"(p));
    return a;
}
__device__ __forceinline__ void ldm_x4(unsigned* r, unsigned addr) {
    asm volatile("ldmatrix.sync.aligned.m8n8.x4.shared.b16 {%0,%1,%2,%3}, [%4];"
                 : "=r"(r[0]), "=r"(r[1]), "=r"(r[2]), "=r"(r[3]) : "r"(addr));
}
__device__ __forceinline__ void mma16816(float* c, const unsigned* a, const unsigned* b) {
    asm volatile(
        "mma.sync.aligned.m16n8k16.row.col.f32.bf16.bf16.f32 "
        "{%0,%1,%2,%3}, {%4,%5,%6,%7}, {%8,%9}, {%0,%1,%2,%3};"
        : "+f"(c[0]), "+f"(c[1]), "+f"(c[2]), "+f"(c[3])
        : "r"(a[0]), "r"(a[1]), "r"(a[2]), "r"(a[3]), "r"(b[0]), "r"(b[1]));
}
// write bf16 hi/lo limb pair (2 adjacent cols) into planes phi/plo
__device__ __forceinline__ void wlimb2(__nv_bfloat16* out, size_t idx,
                                       float v0, float v1, int phi, int plo)
{
    __nv_bfloat16 h0 = __float2bfloat16(v0), h1 = __float2bfloat16(v1);
    float r0 = v0 - __bfloat162float(h0), r1 = v1 - __bfloat162float(h1);
    __nv_bfloat16 l0 = __float2bfloat16(r0), l1 = __float2bfloat16(r1);
    unsigned hp = (unsigned)*(unsigned short*)&h0 | ((unsigned)*(unsigned short*)&h1 << 16);
    unsigned lp = (unsigned)*(unsigned short*)&l0 | ((unsigned)*(unsigned short*)&l1 << 16);
    *(unsigned*)(out + (size_t)phi * UTP + idx) = hp;
    *(unsigned*)(out + (size_t)plo * UTP + idx) = lp;
}

#define MMA12(pcr, pci, af, nih, nil_, brh, brl, bih, bil)                   \
    mma16816(pcr, af[0], brh); mma16816(pcr, af[0], brl);                    \
    mma16816(pcr, af[1], brh); mma16816(pcr, nih,   bih);                    \
    mma16816(pcr, nih,   bil); mma16816(pcr, nil_,  bih);                    \
    mma16816(pci, af[0], bih); mma16816(pci, af[0], bil);                    \
    mma16816(pci, af[1], bih); mma16816(pci, af[2], brh);                    \
    mma16816(pci, af[2], brl); mma16816(pci, af[3], brh);

// ================= tensor NN: C[b] = A(b?) * U[b] =========================
#define APITCH 40
#define APL (64 * APITCH)
#define BPL (128 * APITCH)
#define SMEM_TN ((4 * APL + 4 * BPL) * 2)   // 61440 bytes

__global__ void __launch_bounds__(256, 1)
tensor_nn(const __nv_bfloat16* __restrict__ Ab, int strideAb,
          const __nv_bfloat16* __restrict__ UTb,
          float* __restrict__ Cre, float* __restrict__ Cim,
          __nv_bfloat16* __restrict__ Lbf, int outmode,
          int d, int rest)
{
    extern __shared__ __align__(16) char smem[];
    __nv_bfloat16* As = (__nv_bfloat16*)smem;                 // [4][64][APITCH]
    __nv_bfloat16* Bs = (__nv_bfloat16*)(smem + 4 * APL * 2); // [4][128][APITCH]

    const int tid = threadIdx.x, lane = tid & 31, wid = tid >> 5;
    const int b = blockIdx.z, m0 = blockIdx.y * 64, n0 = blockIdx.x * 128;
    const int wm = wid >> 2, wn = wid & 3;

    const int rsel = lane >> 3, l8 = lane & 7;
    const int aro = (rsel & 1) ? 8 : 0, ako = (rsel & 2) ? 8 : 0;
    const int bko = (rsel & 1) ? 8 : 0, bro = (rsel & 2) ? 8 : 0;

    float cr[2][4][4], ci[2][4][4];
#pragma unroll
    for (int mi = 0; mi < 2; mi++)
#pragma unroll
        for (int ns = 0; ns < 4; ns++)
#pragma unroll
            for (int q = 0; q < 4; q++) { cr[mi][ns][q] = 0.f; ci[mi][ns][q] = 0.f; }

    const int nchunks = d / 32;
    for (int c = 0; c < nchunks; c++) {
        for (int u = tid; u < 1024; u += 256) {
            int p = u >> 8, v = u & 255;
            int r = v >> 2, j = v & 3;
            uint4 s = *(const uint4*)(Ab + (size_t)p * ALP + (size_t)b * strideAb
                                      + (size_t)(m0 + r) * d + c * 32 + j * 8);
            *(uint4*)(As + p * APL + r * APITCH + j * 8) = s;
        }
        for (int u = tid; u < 2048; u += 256) {
            int p = u >> 9, v = u & 511;
            int r = v >> 2, j = v & 3;
            uint4 s = *(const uint4*)(UTb + (size_t)p * UTP + (size_t)b * rest * d
                                      + (size_t)(n0 + r) * d + c * 32 + j * 8);
            *(uint4*)(Bs + p * BPL + r * APITCH + j * 8) = s;
        }
        __syncthreads();

#pragma unroll
        for (int s = 0; s < 2; s++) {
            unsigned bf[4][2][4];
#pragma unroll
            for (int p = 0; p < 4; p++)
#pragma unroll
                for (int gj = 0; gj < 2; gj++) {
                    unsigned addr = smem_u32(Bs + p * BPL
                        + (wn * 32 + gj * 16 + bro + l8) * APITCH + s * 16 + bko);
                    ldm_x4(bf[p][gj], addr);
                }
#pragma unroll
            for (int mi = 0; mi < 2; mi++) {
                unsigned af[4][4];
#pragma unroll
                for (int p = 0; p < 4; p++) {
                    unsigned addr = smem_u32(As + p * APL
                        + (wm * 32 + mi * 16 + aro + l8) * APITCH + s * 16 + ako);
                    ldm_x4(af[p], addr);
                }
                unsigned nih[4], nil_[4];
#pragma unroll
                for (int q = 0; q < 4; q++) {
                    nih[q]  = af[2][q] ^ 0x80008000u;
                    nil_[q] = af[3][q] ^ 0x80008000u;
                }
#pragma unroll
                for (int ns = 0; ns < 4; ns++) {
                    const unsigned* brh = &bf[0][ns >> 1][(ns & 1) * 2];
                    const unsigned* brl = &bf[1][ns >> 1][(ns & 1) * 2];
                    const unsigned* bih = &bf[2][ns >> 1][(ns & 1) * 2];
                    const unsigned* bil = &bf[3][ns >> 1][(ns & 1) * 2];
                    MMA12(cr[mi][ns], ci[mi][ns], af, nih, nil_, brh, brl, bih, bil)
                }
            }
        }
        __syncthreads();
    }

    const int g = lane >> 2, t = lane & 3;
    const size_t base = (size_t)b * d * rest;
#pragma unroll
    for (int mi = 0; mi < 2; mi++) {
        int mrow = m0 + wm * 32 + mi * 16 + g;
#pragma unroll
        for (int ns = 0; ns < 4; ns++) {
            int col = n0 + wn * 32 + ns * 8 + 2 * t;
            if (outmode == 0) {
                *(float2*)(Cre + base + (size_t)mrow * rest + col) =
                    make_float2(cr[mi][ns][0], cr[mi][ns][1]);
                *(float2*)(Cre + base + (size_t)(mrow + 8) * rest + col) =
                    make_float2(cr[mi][ns][2], cr[mi][ns][3]);
                *(float2*)(Cim + base + (size_t)mrow * rest + col) =
                    make_float2(ci[mi][ns][0], ci[mi][ns][1]);
                *(float2*)(Cim + base + (size_t)(mrow + 8) * rest + col) =
                    make_float2(ci[mi][ns][2], ci[mi][ns][3]);
            } else {
                size_t i0 = base + (size_t)mrow * rest + col;
                size_t i1 = base + (size_t)(mrow + 8) * rest + col;
                wlimb2(Lbf, i0, cr[mi][ns][0], cr[mi][ns][1], 0, 1);
                wlimb2(Lbf, i1, cr[mi][ns][2], cr[mi][ns][3], 0, 1);
                wlimb2(Lbf, i0, ci[mi][ns][0], ci[mi][ns][1], 2, 3);
                wlimb2(Lbf, i1, ci[mi][ns][2], ci[mi][ns][3], 2, 3);
            }
        }
    }
}

// ============ tensor NT split-K: P[chunk][b] = L[b] * U[b]^T ==============
// score[i][j] = sum_k L[i][k]*U[j][k]; both operands K-contig row-major.
// CTA 64(M) x 64(N), K-chunk KC, k-steps of 32. 8 warps (2m x 4n), warp 32x16.
#define NTPL (64 * APITCH)      // halves per NT smem plane

__global__ void __launch_bounds__(256, 1)
tensor_nt(const __nv_bfloat16* __restrict__ Lb, const __nv_bfloat16* __restrict__ Ub,
          float* __restrict__ Pre, float* __restrict__ Pim,
          int d, int K, int KC)
{
    __shared__ __align__(16) __nv_bfloat16 As[4 * NTPL], Bs[4 * NTPL];

    const int tid = threadIdx.x, lane = tid & 31, wid = tid >> 5;
    const int bz = blockIdx.z, b = bz & 7, chunk = bz >> 3;
    const int m0 = blockIdx.y * 64, n0 = blockIdx.x * 64;
    const int wm = wid >> 2, wn = wid & 3;

    const int rsel = lane >> 3, l8 = lane & 7;
    const int aro = (rsel & 1) ? 8 : 0, ako = (rsel & 2) ? 8 : 0;
    const int bko = (rsel & 1) ? 8 : 0, bro = (rsel & 2) ? 8 : 0;

    float cr[2][2][4], ci[2][2][4];
#pragma unroll
    for (int mi = 0; mi < 2; mi++)
#pragma unroll
        for (int ns = 0; ns < 2; ns++)
#pragma unroll
            for (int q = 0; q < 4; q++) { cr[mi][ns][q] = 0.f; ci[mi][ns][q] = 0.f; }

    const size_t bb = (size_t)b * d * K;
    const int kbeg = chunk * KC;
    const int nchunks = KC / 32;

    for (int c = 0; c < nchunks; c++) {
        const int koff = kbeg + c * 32;
        for (int u = tid; u < 1024; u += 256) {
            int p = u >> 8, v = u & 255;
            int r = v >> 2, j = v & 3;
            uint4 sa = *(const uint4*)(Lb + (size_t)p * UTP + bb
                                       + (size_t)(m0 + r) * K + koff + j * 8);
            *(uint4*)(As + p * NTPL + r * APITCH + j * 8) = sa;
            uint4 sb = *(const uint4*)(Ub + (size_t)p * UTP + bb
                                       + (size_t)(n0 + r) * K + koff + j * 8);
            *(uint4*)(Bs + p * NTPL + r * APITCH + j * 8) = sb;
        }
        __syncthreads();

#pragma unroll
        for (int s = 0; s < 2; s++) {
            unsigned bf[4][4];
#pragma unroll
            for (int p = 0; p < 4; p++) {
                unsigned addr = smem_u32(Bs + p * NTPL
                    + (wn * 16 + bro + l8) * APITCH + s * 16 + bko);
                ldm_x4(bf[p], addr);
            }
#pragma unroll
            for (int mi = 0; mi < 2; mi++) {
                unsigned af[4][4];
#pragma unroll
                for (int p = 0; p < 4; p++) {
                    unsigned addr = smem_u32(As + p * NTPL
                        + (wm * 32 + mi * 16 + aro + l8) * APITCH + s * 16 + ako);
                    ldm_x4(af[p], addr);
                }
                unsigned nih[4], nil_[4];
#pragma unroll
                for (int q = 0; q < 4; q++) {
                    nih[q]  = af[2][q] ^ 0x80008000u;
                    nil_[q] = af[3][q] ^ 0x80008000u;
                }
#pragma unroll
                for (int ns = 0; ns < 2; ns++) {
                    const unsigned* brh = &bf[0][ns * 2];
                    const unsigned* brl = &bf[1][ns * 2];
                    const unsigned* bih = &bf[2][ns * 2];
                    const unsigned* bil = &bf[3][ns * 2];
                    MMA12(cr[mi][ns], ci[mi][ns], af, nih, nil_, brh, brl, bih, bil)
                }
            }
        }
        __syncthreads();
    }

    const int g = lane >> 2, t = lane & 3;
    const size_t off = (size_t)(chunk * BATCH + b) * d * d;
#pragma unroll
    for (int mi = 0; mi < 2; mi++) {
        int mrow = m0 + wm * 32 + mi * 16 + g;
#pragma unroll
        for (int ns = 0; ns < 2; ns++) {
            int col = n0 + wn * 16 + ns * 8 + 2 * t;
            *(float2*)(Pre + off + (size_t)mrow * d + col) =
                make_float2(cr[mi][ns][0], cr[mi][ns][1]);
            *(float2*)(Pre + off + (size_t)(mrow + 8) * d + col) =
                make_float2(cr[mi][ns][2], cr[mi][ns][3]);
            *(float2*)(Pim + off + (size_t)mrow * d + col) =
                make_float2(ci[mi][ns][0], ci[mi][ns][1]);
            *(float2*)(Pim + off + (size_t)(mrow + 8) * d + col) =
                make_float2(ci[mi][ns][2], ci[mi][ns][3]);
        }
    }
}

// ---------------- fused split-K reduce + softmax(|s|/scale)*phase ---------
__global__ void softmax_fused(const float* __restrict__ Pre, const float* __restrict__ Pim,
                              float* __restrict__ Mre, float* __restrict__ Mim,
                              int d, int n, int nchunks,
                              const float* __restrict__ logtau, float sfac)
{
    const int row = blockIdx.x;
    const int j   = threadIdx.x;
    const int idx = row * d + j;

    float sr = 0.f, si = 0.f;
    for (int c = 0; c < nchunks; c++) {
        sr += Pre[(size_t)c * n + idx];
        si += Pim[(size_t)c * n + idx];
    }
    const float mag = sqrtf(sr * sr + si * si);

    const float tau   = fmaxf(expf(logtau[0]), 1e-8f);
    const float scale = tau * sfac;
    const float logit = mag / scale;

    __shared__ float wred[4];
    __shared__ float wsum[4];
    const int warp = j >> 5, lane = j & 31, nw = d >> 5;

    float v = logit;
#pragma unroll
    for (int o = 16; o > 0; o >>= 1) v = fmaxf(v, __shfl_xor_sync(0xffffffffu, v, o));
    if (lane == 0) wred[warp] = v;
    __syncthreads();
    float mx = wred[0];
    for (int w = 1; w < nw; w++) mx = fmaxf(mx, wred[w]);

    const float e = expf(logit - mx);
    float s_ = e;
#pragma unroll
    for (int o = 16; o > 0; o >>= 1) s_ += __shfl_xor_sync(0xffffffffu, s_, o);
    if (lane == 0) wsum[warp] = s_;
    __syncthreads();
    float tot = 0.f;
    for (int w = 0; w < nw; w++) tot += wsum[w];

    const float routing = e / tot;
    float pr, pi;
    if (mag > 1e-8f) { pr = sr / mag; pi = si / mag; }
    else             { pr = 1.f;      pi = 0.f; }
    Mre[(size_t)row * d + j] = routing * pr;
    Mim[(size_t)row * d + j] = routing * pi;
}

// ---------------- permutes (unchanged) ------------------------------------
__global__ void perm_swap01(const float4* __restrict__ s4re, const float4* __restrict__ s4im,
                            float4* __restrict__ d4re, float4* __restrict__ d4im)
{
    int t = blockIdx.x * 256 + threadIdx.x;
    int k4 = t & 15;
    int q  = (t >> 4) & 127;
    int p  = (t >> 11) & 127;
    int b  = t >> 18;
    int src = ((((b << 7) | q) << 7) | p) << 4 | k4;
    d4re[t] = s4re[src];
    d4im[t] = s4im[src];
}

__global__ void perm_transpose(const float* __restrict__ sre, const float* __restrict__ sim,
                               float* __restrict__ dre, float* __restrict__ dim_,
                               int R, int C)
{
    __shared__ float tre[32][33], tim[32][33];
    const int b  = blockIdx.z;
    const int r0 = blockIdx.y * 32;
    const int c0 = blockIdx.x * 32;
    const float* sr_ = sre + (size_t)b * R * C;
    const float* si_ = sim + (size_t)b * R * C;
    float*       dr_ = dre + (size_t)b * R * C;
    float*       di_ = dim_ + (size_t)b * R * C;
    const int x = threadIdx.x, y = threadIdx.y;
#pragma unroll
    for (int i = y; i < 32; i += 8) {
        tre[i][x] = sr_[(size_t)(r0 + i) * C + c0 + x];
        tim[i][x] = si_[(size_t)(r0 + i) * C + c0 + x];
    }
    __syncthreads();
#pragma unroll
    for (int i = y; i < 32; i += 8) {
        dr_[(size_t)(c0 + i) * R + r0 + x] = tre[x][i];
        di_[(size_t)(c0 + i) * R + r0 + x] = tim[x][i];
    }
}

// --------------------------------------------------------------------------
extern "C" void kernel_launch(void* const* d_in, const int* in_sizes, int n_in,
                              void* d_out, int out_size)
{
    (void)in_sizes; (void)n_in; (void)out_size;
    const float* xre  = (const float*)d_in[0];
    const float* xim  = (const float*)d_in[1];
    const float* wre[3] = {(const float*)d_in[2], (const float*)d_in[4], (const float*)d_in[6]};
    const float* wim[3] = {(const float*)d_in[3], (const float*)d_in[5], (const float*)d_in[7]};
    const float* ltau = (const float*)d_in[8];
    float* out_re = (float*)d_out;
    float* out_im = out_re + (size_t)NTOT;

    float *s_re, *s_im, *u_re, *u_im, *l_re, *l_im, *p_re, *p_im, *m_re, *m_im;
    __nv_bfloat16 *abf, *utbf, *ubf, *lbf;
    cudaGetSymbolAddress((void**)&s_re,  g_s_re);
    cudaGetSymbolAddress((void**)&s_im,  g_s_im);
    cudaGetSymbolAddress((void**)&u_re,  g_u_re);
    cudaGetSymbolAddress((void**)&u_im,  g_u_im);
    cudaGetSymbolAddress((void**)&l_re,  g_l_re);
    cudaGetSymbolAddress((void**)&l_im,  g_l_im);
    cudaGetSymbolAddress((void**)&p_re,  g_p_re);
    cudaGetSymbolAddress((void**)&p_im,  g_p_im);
    cudaGetSymbolAddress((void**)&m_re,  g_m_re);
    cudaGetSymbolAddress((void**)&m_im,  g_m_im);
    cudaGetSymbolAddress((void**)&abf,   g_abf);
    cudaGetSymbolAddress((void**)&utbf,  g_utbf);
    cudaGetSymbolAddress((void**)&ubf,   g_ubf);
    cudaGetSymbolAddress((void**)&lbf,   g_lbf);

    cudaFuncSetAttribute(tensor_nn, cudaFuncAttributeMaxDynamicSharedMemorySize, SMEM_TN);

    for (int mode = 0; mode < 3; mode++) {
        const int d    = (mode < 2) ? 128 : 64;
        const int rest = SS / d;
        const float sfac = sqrtf((float)SS / (float)d);

        // ---- unfold into u (mode0: u = x directly) ----
        const float *cu_re, *cu_im;
        if (mode == 0) { cu_re = xre; cu_im = xim; }
        else if (mode == 1) {
            perm_swap01<<<(NTOT / 4) / 256, 256>>>((const float4*)s_re, (const float4*)s_im,
                                                   (float4*)u_re, (float4*)u_im);
            cu_re = u_re; cu_im = u_im;
        } else {
            dim3 gt(64 / 32, 16384 / 32, BATCH);
            perm_transpose<<<gt, dim3(32, 8)>>>(s_re, s_im, u_re, u_im, 16384, 64);
            cu_re = u_re; cu_im = u_im;
        }

        // ---- conversions: UT limbs + U limbs + W limbs ----
        conv_ut<<<dim3(rest / 32, d / 32, BATCH), dim3(32, 8)>>>(cu_re, cu_im, utbf, ubf, d, rest);
        conv_limbs_A<<<(d * d + 255) / 256, 256>>>(wre[mode], wim[mode], abf, d * d);

        // ---- NN1 (tensor): l = W * u  -> bf16 limb planes directly ----
        dim3 gnn(rest / 128, d / 64, BATCH);
        tensor_nn<<<gnn, 256, SMEM_TN>>>(abf, 0, utbf, l_re, l_im, lbf, 1, d, rest);

        // ---- NT (tensor split-K): score partials = l * u^T ----
        const int NC = (mode < 2) ? 32 : 64;
        const int KC = rest / NC;               // 256
        dim3 g2(d / 64, d / 64, BATCH * NC);
        tensor_nt<<<g2, 256>>>(lbf, ubf, p_re, p_im, d, rest, KC);

        // ---- softmax + phase -> m ----
        const int n = BATCH * d * d;
        softmax_fused<<<BATCH * d, d>>>(p_re, p_im, m_re, m_im, d, n, NC, ltau, sfac);

        // ---- NN2 (tensor): mixed = m * u (fp32 out) ----
        conv_limbs_A<<<(n + 255) / 256, 256>>>(m_re, m_im, abf, n);
        float* o_re = (mode == 0) ? s_re : l_re;
        float* o_im = (mode == 0) ? s_im : l_im;
        tensor_nn<<<gnn, 256, SMEM_TN>>>(abf, d * d, utbf, o_re, o_im, lbf, 0, d, rest);

        // ---- fold back ----
        if (mode == 1) {
            perm_swap01<<<(NTOT / 4) / 256, 256>>>((const float4*)l_re, (const float4*)l_im,
                                                   (float4*)s_re, (float4*)s_im);
        } else if (mode == 2) {
            dim3 gt2(16384 / 32, 64 / 32, BATCH);
            perm_transpose<<<gt2, dim3(32, 8)>>>(l_re, l_im, out_re, out_im, 64, 16384);
        }
    }
}

// round 14
// speedup vs baseline: 1.3844x; 1.3844x over previous
#include <cuda_runtime.h>
#include <cuda_bf16.h>
#include <math.h>

#define BATCH 8
#define SS 1048576              // 128*128*64
#define NTOT (BATCH * SS)       // 8388608 per component
#define ALP 131072              // A-limb plane stride (B*128*128 max)
#define UTP NTOT                // big limb plane stride

// ---------------- scratch (device globals; no allocation) ----------------
__device__ float g_s_re[NTOT];
__device__ float g_s_im[NTOT];
__device__ float g_u_re[NTOT];
__device__ float g_u_im[NTOT];
__device__ float g_l_re[NTOT];
__device__ float g_l_im[NTOT];
__device__ float g_p_re[4194304];
__device__ float g_p_im[4194304];
__device__ float g_m_re[131072];
__device__ float g_m_im[131072];
__device__ __nv_bfloat16 g_abf[4 * ALP];   // A limbs: rhi,rlo,ihi,ilo
__device__ __nv_bfloat16 g_utbf[4 * UTP];  // U^T limbs (B,rest,d)
__device__ __nv_bfloat16 g_ubf[4 * UTP];   // U  limbs (B,d,rest)
__device__ __nv_bfloat16 g_lbf[4 * UTP];   // L  limbs (B,d,rest)

typedef unsigned long long u64;

// ================= limb conversion kernels ================================
__global__ void conv_limbs_A(const float* __restrict__ re, const float* __restrict__ im,
                             __nv_bfloat16* __restrict__ out, int n)
{
    int i = blockIdx.x * 256 + threadIdx.x;
    if (i >= n) return;
    float x = re[i];
    __nv_bfloat16 h = __float2bfloat16(x);
    out[0 * ALP + i] = h;
    out[1 * ALP + i] = __float2bfloat16(x - __bfloat162float(h));
    float y = im[i];
    __nv_bfloat16 ih = __float2bfloat16(y);
    out[2 * ALP + i] = ih;
    out[3 * ALP + i] = __float2bfloat16(y - __bfloat162float(ih));
}

// U (B,d,rest) fp32 -> UT limbs (B,rest,d) AND U limbs (B,d,rest)
__global__ void conv_ut(const float* __restrict__ ure, const float* __restrict__ uim,
                        __nv_bfloat16* __restrict__ outT, __nv_bfloat16* __restrict__ outU,
                        int d, int rest)
{
    __shared__ float tr[32][33], ti[32][33];
    const int b  = blockIdx.z;
    const int k0 = blockIdx.y * 32;
    const int n0 = blockIdx.x * 32;
    const size_t ib = (size_t)b * d * rest;
    const size_t ob = (size_t)b * rest * d;
    const int x = threadIdx.x, y = threadIdx.y;
#pragma unroll
    for (int i = y; i < 32; i += 8) {
        size_t si = ib + (size_t)(k0 + i) * rest + n0 + x;
        float xr = ure[si], xi = uim[si];
        tr[i][x] = xr; ti[i][x] = xi;
        __nv_bfloat16 rh = __float2bfloat16(xr);
        __nv_bfloat16 ihh = __float2bfloat16(xi);
        outU[0 * (size_t)UTP + si] = rh;
        outU[1 * (size_t)UTP + si] = __float2bfloat16(xr - __bfloat162float(rh));
        outU[2 * (size_t)UTP + si] = ihh;
        outU[3 * (size_t)UTP + si] = __float2bfloat16(xi - __bfloat162float(ihh));
    }
    __syncthreads();
#pragma unroll
    for (int i = y; i < 32; i += 8) {
        size_t o = ob + (size_t)(n0 + i) * d + k0 + x;
        float xr = tr[x][i], xi = ti[x][i];
        __nv_bfloat16 rh = __float2bfloat16(xr);
        __nv_bfloat16 ihh = __float2bfloat16(xi);
        outT[0 * (size_t)UTP + o] = rh;
        outT[1 * (size_t)UTP + o] = __float2bfloat16(xr - __bfloat162float(rh));
        outT[2 * (size_t)UTP + o] = ihh;
        outT[3 * (size_t)UTP + o] = __float2bfloat16(xi - __bfloat162float(ihh));
    }
}

// ================= mma.sync / cp.async helpers ============================
__device__ __forceinline__ unsigned smem_u32(const void* p) {
    unsigned a;
    asm("{ .reg .u64 t; cvta.to.shared.u64 t, %1; cvt.u32.u64 %0, t; }"
        : "=r"(a) : "l"(p));
    return a;
}
__device__ __forceinline__ void cpasync16(unsigned saddr, const void* g) {
    asm volatile("cp.async.cg.shared.global [%0], [%1], 16;" :: "r"(saddr), "l"(g));
}
#define CP_COMMIT() asm volatile("cp.async.commit_group;" ::: "memory")
#define CP_WAIT0()  asm volatile("cp.async.wait_group 0;" ::: "memory")
__device__ __forceinline__ void ldm_x4(unsigned* r, unsigned addr) {
    asm volatile("ldmatrix.sync.aligned.m8n8.x4.shared.b16 {%0,%1,%2,%3}, [%4];"
                 : "=r"(r[0]), "=r"(r[1]), "=r"(r[2]), "=r"(r[3]) : "r"(addr));
}
__device__ __forceinline__ void mma16816(float* c, const unsigned* a, const unsigned* b) {
    asm volatile(
        "mma.sync.aligned.m16n8k16.row.col.f32.bf16.bf16.f32 "
        "{%0,%1,%2,%3}, {%4,%5,%6,%7}, {%8,%9}, {%0,%1,%2,%3};"
        : "+f"(c[0]), "+f"(c[1]), "+f"(c[2]), "+f"(c[3])
        : "r"(a[0]), "r"(a[1]), "r"(a[2]), "r"(a[3]), "r"(b[0]), "r"(b[1]));
}
__device__ __forceinline__ void wlimb2(__nv_bfloat16* out, size_t idx,
                                       float v0, float v1, int phi, int plo)
{
    __nv_bfloat16 h0 = __float2bfloat16(v0), h1 = __float2bfloat16(v1);
    float r0 = v0 - __bfloat162float(h0), r1 = v1 - __bfloat162float(h1);
    __nv_bfloat16 l0 = __float2bfloat16(r0), l1 = __float2bfloat16(r1);
    unsigned hp = (unsigned)*(unsigned short*)&h0 | ((unsigned)*(unsigned short*)&h1 << 16);
    unsigned lp = (unsigned)*(unsigned short*)&l0 | ((unsigned)*(unsigned short*)&l1 << 16);
    *(unsigned*)(out + (size_t)phi * UTP + idx) = hp;
    *(unsigned*)(out + (size_t)plo * UTP + idx) = lp;
}

#define MMA12(pcr, pci, af, nih, nil_, brh, brl, bih, bil)                   \
    mma16816(pcr, af[0], brh); mma16816(pcr, af[0], brl);                    \
    mma16816(pcr, af[1], brh); mma16816(pcr, nih,   bih);                    \
    mma16816(pcr, nih,   bil); mma16816(pcr, nil_,  bih);                    \
    mma16816(pci, af[0], bih); mma16816(pci, af[0], bil);                    \
    mma16816(pci, af[1], bih); mma16816(pci, af[2], brh);                    \
    mma16816(pci, af[2], brl); mma16816(pci, af[3], brh);

// ================= tensor NN: C[b] = A(b?) * U[b] =========================
// double-buffered cp.async pipeline; CTA 64x128, 8 warps (2m x 4n)
#define APITCH 40
#define APL (64 * APITCH)
#define BPL (128 * APITCH)
#define NNBUF (4 * APL + 4 * BPL)           // halves per pipeline buffer
#define SMEM_TN (2 * NNBUF * 2)             // 122880 bytes

__global__ void __launch_bounds__(256, 1)
tensor_nn(const __nv_bfloat16* __restrict__ Ab, int strideAb,
          const __nv_bfloat16* __restrict__ UTb,
          float* __restrict__ Cre, float* __restrict__ Cim,
          __nv_bfloat16* __restrict__ Lbf, int outmode,
          int d, int rest)
{
    extern __shared__ __align__(16) char smem[];
    __nv_bfloat16* buf[2] = { (__nv_bfloat16*)smem, (__nv_bfloat16*)smem + NNBUF };

    const int tid = threadIdx.x, lane = tid & 31, wid = tid >> 5;
    const int b = blockIdx.z, m0 = blockIdx.y * 64, n0 = blockIdx.x * 128;
    const int wm = wid >> 2, wn = wid & 3;

    const int rsel = lane >> 3, l8 = lane & 7;
    const int aro = (rsel & 1) ? 8 : 0, ako = (rsel & 2) ? 8 : 0;
    const int bko = (rsel & 1) ? 8 : 0, bro = (rsel & 2) ? 8 : 0;

    // per-thread copy roles (precomputed)
    const size_t abase = (size_t)b * strideAb;
    const size_t bbase = (size_t)b * rest * d;

    float cr[2][4][4], ci[2][4][4];
#pragma unroll
    for (int mi = 0; mi < 2; mi++)
#pragma unroll
        for (int ns = 0; ns < 4; ns++)
#pragma unroll
            for (int q = 0; q < 4; q++) { cr[mi][ns][q] = 0.f; ci[mi][ns][q] = 0.f; }

    const int nchunks = d / 32;

#define NN_ISSUE(cc, bx)                                                       \
    {                                                                          \
        __nv_bfloat16* As_ = buf[bx];                                          \
        __nv_bfloat16* Bs_ = buf[bx] + 4 * APL;                                \
        for (int u = tid; u < 1024; u += 256) {                                \
            int p = u >> 8, v = u & 255;                                       \
            int r = v >> 2, j = v & 3;                                         \
            cpasync16(smem_u32(As_ + p * APL + r * APITCH + j * 8),            \
                      Ab + (size_t)p * ALP + abase + (size_t)(m0 + r) * d      \
                      + (cc) * 32 + j * 8);                                    \
        }                                                                      \
        for (int u = tid; u < 2048; u += 256) {                                \
            int p = u >> 9, v = u & 511;                                       \
            int r = v >> 2, j = v & 3;                                         \
            cpasync16(smem_u32(Bs_ + p * BPL + r * APITCH + j * 8),            \
                      UTb + (size_t)p * UTP + bbase + (size_t)(n0 + r) * d     \
                      + (cc) * 32 + j * 8);                                    \
        }                                                                      \
        CP_COMMIT();                                                           \
    }

    NN_ISSUE(0, 0)
    for (int c = 0; c < nchunks; c++) {
        CP_WAIT0();
        __syncthreads();
        if (c + 1 < nchunks) NN_ISSUE(c + 1, (c + 1) & 1)

        __nv_bfloat16* As = buf[c & 1];
        __nv_bfloat16* Bs = buf[c & 1] + 4 * APL;
#pragma unroll
        for (int s = 0; s < 2; s++) {
            unsigned bf[4][2][4];
#pragma unroll
            for (int p = 0; p < 4; p++)
#pragma unroll
                for (int gj = 0; gj < 2; gj++) {
                    unsigned addr = smem_u32(Bs + p * BPL
                        + (wn * 32 + gj * 16 + bro + l8) * APITCH + s * 16 + bko);
                    ldm_x4(bf[p][gj], addr);
                }
#pragma unroll
            for (int mi = 0; mi < 2; mi++) {
                unsigned af[4][4];
#pragma unroll
                for (int p = 0; p < 4; p++) {
                    unsigned addr = smem_u32(As + p * APL
                        + (wm * 32 + mi * 16 + aro + l8) * APITCH + s * 16 + ako);
                    ldm_x4(af[p], addr);
                }
                unsigned nih[4], nil_[4];
#pragma unroll
                for (int q = 0; q < 4; q++) {
                    nih[q]  = af[2][q] ^ 0x80008000u;
                    nil_[q] = af[3][q] ^ 0x80008000u;
                }
#pragma unroll
                for (int ns = 0; ns < 4; ns++) {
                    const unsigned* brh = &bf[0][ns >> 1][(ns & 1) * 2];
                    const unsigned* brl = &bf[1][ns >> 1][(ns & 1) * 2];
                    const unsigned* bih = &bf[2][ns >> 1][(ns & 1) * 2];
                    const unsigned* bil = &bf[3][ns >> 1][(ns & 1) * 2];
                    MMA12(cr[mi][ns], ci[mi][ns], af, nih, nil_, brh, brl, bih, bil)
                }
            }
        }
        __syncthreads();
    }

    const int g = lane >> 2, t = lane & 3;
    const size_t base = (size_t)b * d * rest;
#pragma unroll
    for (int mi = 0; mi < 2; mi++) {
        int mrow = m0 + wm * 32 + mi * 16 + g;
#pragma unroll
        for (int ns = 0; ns < 4; ns++) {
            int col = n0 + wn * 32 + ns * 8 + 2 * t;
            if (outmode == 0) {
                *(float2*)(Cre + base + (size_t)mrow * rest + col) =
                    make_float2(cr[mi][ns][0], cr[mi][ns][1]);
                *(float2*)(Cre + base + (size_t)(mrow + 8) * rest + col) =
                    make_float2(cr[mi][ns][2], cr[mi][ns][3]);
                *(float2*)(Cim + base + (size_t)mrow * rest + col) =
                    make_float2(ci[mi][ns][0], ci[mi][ns][1]);
                *(float2*)(Cim + base + (size_t)(mrow + 8) * rest + col) =
                    make_float2(ci[mi][ns][2], ci[mi][ns][3]);
            } else {
                size_t i0 = base + (size_t)mrow * rest + col;
                size_t i1 = base + (size_t)(mrow + 8) * rest + col;
                wlimb2(Lbf, i0, cr[mi][ns][0], cr[mi][ns][1], 0, 1);
                wlimb2(Lbf, i1, cr[mi][ns][2], cr[mi][ns][3], 0, 1);
                wlimb2(Lbf, i0, ci[mi][ns][0], ci[mi][ns][1], 2, 3);
                wlimb2(Lbf, i1, ci[mi][ns][2], ci[mi][ns][3], 2, 3);
            }
        }
    }
}

// ============ tensor NT split-K: P[chunk][b] = L[b] * U[b]^T ==============
// double-buffered cp.async; CTA 64x64, 8 warps (2m x 4n), warp 32x16
#define NTPL (64 * APITCH)
#define NTBUF (8 * NTPL)                     // halves per buffer (As+Bs)
#define SMEM_NT (2 * NTBUF * 2)              // 81920 bytes

__global__ void __launch_bounds__(256, 1)
tensor_nt(const __nv_bfloat16* __restrict__ Lb, const __nv_bfloat16* __restrict__ Ub,
          float* __restrict__ Pre, float* __restrict__ Pim,
          int d, int K, int KC)
{
    extern __shared__ __align__(16) char smem[];
    __nv_bfloat16* buf[2] = { (__nv_bfloat16*)smem, (__nv_bfloat16*)smem + NTBUF };

    const int tid = threadIdx.x, lane = tid & 31, wid = tid >> 5;
    const int bz = blockIdx.z, b = bz & 7, chunk = bz >> 3;
    const int m0 = blockIdx.y * 64, n0 = blockIdx.x * 64;
    const int wm = wid >> 2, wn = wid & 3;

    const int rsel = lane >> 3, l8 = lane & 7;
    const int aro = (rsel & 1) ? 8 : 0, ako = (rsel & 2) ? 8 : 0;
    const int bko = (rsel & 1) ? 8 : 0, bro = (rsel & 2) ? 8 : 0;

    float cr[2][2][4], ci[2][2][4];
#pragma unroll
    for (int mi = 0; mi < 2; mi++)
#pragma unroll
        for (int ns = 0; ns < 2; ns++)
#pragma unroll
            for (int q = 0; q < 4; q++) { cr[mi][ns][q] = 0.f; ci[mi][ns][q] = 0.f; }

    const size_t bb = (size_t)b * d * K;
    const int kbeg = chunk * KC;
    const int nchunks = KC / 32;

#define NT_ISSUE(cc, bx)                                                       \
    {                                                                          \
        __nv_bfloat16* As_ = buf[bx];                                          \
        __nv_bfloat16* Bs_ = buf[bx] + 4 * NTPL;                               \
        const int ko = kbeg + (cc) * 32;                                       \
        for (int u = tid; u < 1024; u += 256) {                                \
            int p = u >> 8, v = u & 255;                                       \
            int r = v >> 2, j = v & 3;                                         \
            cpasync16(smem_u32(As_ + p * NTPL + r * APITCH + j * 8),           \
                      Lb + (size_t)p * UTP + bb + (size_t)(m0 + r) * K + ko + j * 8); \
            cpasync16(smem_u32(Bs_ + p * NTPL + r * APITCH + j * 8),           \
                      Ub + (size_t)p * UTP + bb + (size_t)(n0 + r) * K + ko + j * 8); \
        }                                                                      \
        CP_COMMIT();                                                           \
    }

    NT_ISSUE(0, 0)
    for (int c = 0; c < nchunks; c++) {
        CP_WAIT0();
        __syncthreads();
        if (c + 1 < nchunks) NT_ISSUE(c + 1, (c + 1) & 1)

        __nv_bfloat16* As = buf[c & 1];
        __nv_bfloat16* Bs = buf[c & 1] + 4 * NTPL;
#pragma unroll
        for (int s = 0; s < 2; s++) {
            unsigned bf[4][4];
#pragma unroll
            for (int p = 0; p < 4; p++) {
                unsigned addr = smem_u32(Bs + p * NTPL
                    + (wn * 16 + bro + l8) * APITCH + s * 16 + bko);
                ldm_x4(bf[p], addr);
            }
#pragma unroll
            for (int mi = 0; mi < 2; mi++) {
                unsigned af[4][4];
#pragma unroll
                for (int p = 0; p < 4; p++) {
                    unsigned addr = smem_u32(As + p * NTPL
                        + (wm * 32 + mi * 16 + aro + l8) * APITCH + s * 16 + ako);
                    ldm_x4(af[p], addr);
                }
                unsigned nih[4], nil_[4];
#pragma unroll
                for (int q = 0; q < 4; q++) {
                    nih[q]  = af[2][q] ^ 0x80008000u;
                    nil_[q] = af[3][q] ^ 0x80008000u;
                }
#pragma unroll
                for (int ns = 0; ns < 2; ns++) {
                    const unsigned* brh = &bf[0][ns * 2];
                    const unsigned* brl = &bf[1][ns * 2];
                    const unsigned* bih = &bf[2][ns * 2];
                    const unsigned* bil = &bf[3][ns * 2];
                    MMA12(cr[mi][ns], ci[mi][ns], af, nih, nil_, brh, brl, bih, bil)
                }
            }
        }
        __syncthreads();
    }

    const int g = lane >> 2, t = lane & 3;
    const size_t off = (size_t)(chunk * BATCH + b) * d * d;
#pragma unroll
    for (int mi = 0; mi < 2; mi++) {
        int mrow = m0 + wm * 32 + mi * 16 + g;
#pragma unroll
        for (int ns = 0; ns < 2; ns++) {
            int col = n0 + wn * 16 + ns * 8 + 2 * t;
            *(float2*)(Pre + off + (size_t)mrow * d + col) =
                make_float2(cr[mi][ns][0], cr[mi][ns][1]);
            *(float2*)(Pre + off + (size_t)(mrow + 8) * d + col) =
                make_float2(cr[mi][ns][2], cr[mi][ns][3]);
            *(float2*)(Pim + off + (size_t)mrow * d + col) =
                make_float2(ci[mi][ns][0], ci[mi][ns][1]);
            *(float2*)(Pim + off + (size_t)(mrow + 8) * d + col) =
                make_float2(ci[mi][ns][2], ci[mi][ns][3]);
        }
    }
}

// ---------------- fused split-K reduce + softmax(|s|/scale)*phase ---------
__global__ void softmax_fused(const float* __restrict__ Pre, const float* __restrict__ Pim,
                              float* __restrict__ Mre, float* __restrict__ Mim,
                              int d, int n, int nchunks,
                              const float* __restrict__ logtau, float sfac)
{
    const int row = blockIdx.x;
    const int j   = threadIdx.x;
    const int idx = row * d + j;

    float sr = 0.f, si = 0.f;
    for (int c = 0; c < nchunks; c++) {
        sr += Pre[(size_t)c * n + idx];
        si += Pim[(size_t)c * n + idx];
    }
    const float mag = sqrtf(sr * sr + si * si);

    const float tau   = fmaxf(expf(logtau[0]), 1e-8f);
    const float scale = tau * sfac;
    const float logit = mag / scale;

    __shared__ float wred[4];
    __shared__ float wsum[4];
    const int warp = j >> 5, lane = j & 31, nw = d >> 5;

    float v = logit;
#pragma unroll
    for (int o = 16; o > 0; o >>= 1) v = fmaxf(v, __shfl_xor_sync(0xffffffffu, v, o));
    if (lane == 0) wred[warp] = v;
    __syncthreads();
    float mx = wred[0];
    for (int w = 1; w < nw; w++) mx = fmaxf(mx, wred[w]);

    const float e = expf(logit - mx);
    float s_ = e;
#pragma unroll
    for (int o = 16; o > 0; o >>= 1) s_ += __shfl_xor_sync(0xffffffffu, s_, o);
    if (lane == 0) wsum[warp] = s_;
    __syncthreads();
    float tot = 0.f;
    for (int w = 0; w < nw; w++) tot += wsum[w];

    const float routing = e / tot;
    float pr, pi;
    if (mag > 1e-8f) { pr = sr / mag; pi = si / mag; }
    else             { pr = 1.f;      pi = 0.f; }
    Mre[(size_t)row * d + j] = routing * pr;
    Mim[(size_t)row * d + j] = routing * pi;
}

// ---------------- permutes (unchanged) ------------------------------------
__global__ void perm_swap01(const float4* __restrict__ s4re, const float4* __restrict__ s4im,
                            float4* __restrict__ d4re, float4* __restrict__ d4im)
{
    int t = blockIdx.x * 256 + threadIdx.x;
    int k4 = t & 15;
    int q  = (t >> 4) & 127;
    int p  = (t >> 11) & 127;
    int b  = t >> 18;
    int src = ((((b << 7) | q) << 7) | p) << 4 | k4;
    d4re[t] = s4re[src];
    d4im[t] = s4im[src];
}

__global__ void perm_transpose(const float* __restrict__ sre, const float* __restrict__ sim,
                               float* __restrict__ dre, float* __restrict__ dim_,
                               int R, int C)
{
    __shared__ float tre[32][33], tim[32][33];
    const int b  = blockIdx.z;
    const int r0 = blockIdx.y * 32;
    const int c0 = blockIdx.x * 32;
    const float* sr_ = sre + (size_t)b * R * C;
    const float* si_ = sim + (size_t)b * R * C;
    float*       dr_ = dre + (size_t)b * R * C;
    float*       di_ = dim_ + (size_t)b * R * C;
    const int x = threadIdx.x, y = threadIdx.y;
#pragma unroll
    for (int i = y; i < 32; i += 8) {
        tre[i][x] = sr_[(size_t)(r0 + i) * C + c0 + x];
        tim[i][x] = si_[(size_t)(r0 + i) * C + c0 + x];
    }
    __syncthreads();
#pragma unroll
    for (int i = y; i < 32; i += 8) {
        dr_[(size_t)(c0 + i) * R + r0 + x] = tre[x][i];
        di_[(size_t)(c0 + i) * R + r0 + x] = tim[x][i];
    }
}

// --------------------------------------------------------------------------
extern "C" void kernel_launch(void* const* d_in, const int* in_sizes, int n_in,
                              void* d_out, int out_size)
{
    (void)in_sizes; (void)n_in; (void)out_size;
    const float* xre  = (const float*)d_in[0];
    const float* xim  = (const float*)d_in[1];
    const float* wre[3] = {(const float*)d_in[2], (const float*)d_in[4], (const float*)d_in[6]};
    const float* wim[3] = {(const float*)d_in[3], (const float*)d_in[5], (const float*)d_in[7]};
    const float* ltau = (const float*)d_in[8];
    float* out_re = (float*)d_out;
    float* out_im = out_re + (size_t)NTOT;

    float *s_re, *s_im, *u_re, *u_im, *l_re, *l_im, *p_re, *p_im, *m_re, *m_im;
    __nv_bfloat16 *abf, *utbf, *ubf, *lbf;
    cudaGetSymbolAddress((void**)&s_re,  g_s_re);
    cudaGetSymbolAddress((void**)&s_im,  g_s_im);
    cudaGetSymbolAddress((void**)&u_re,  g_u_re);
    cudaGetSymbolAddress((void**)&u_im,  g_u_im);
    cudaGetSymbolAddress((void**)&l_re,  g_l_re);
    cudaGetSymbolAddress((void**)&l_im,  g_l_im);
    cudaGetSymbolAddress((void**)&p_re,  g_p_re);
    cudaGetSymbolAddress((void**)&p_im,  g_p_im);
    cudaGetSymbolAddress((void**)&m_re,  g_m_re);
    cudaGetSymbolAddress((void**)&m_im,  g_m_im);
    cudaGetSymbolAddress((void**)&abf,   g_abf);
    cudaGetSymbolAddress((void**)&utbf,  g_utbf);
    cudaGetSymbolAddress((void**)&ubf,   g_ubf);
    cudaGetSymbolAddress((void**)&lbf,   g_lbf);

    cudaFuncSetAttribute(tensor_nn, cudaFuncAttributeMaxDynamicSharedMemorySize, SMEM_TN);
    cudaFuncSetAttribute(tensor_nt, cudaFuncAttributeMaxDynamicSharedMemorySize, SMEM_NT);

    for (int mode = 0; mode < 3; mode++) {
        const int d    = (mode < 2) ? 128 : 64;
        const int rest = SS / d;
        const float sfac = sqrtf((float)SS / (float)d);

        // ---- unfold into u (mode0: u = x directly) ----
        const float *cu_re, *cu_im;
        if (mode == 0) { cu_re = xre; cu_im = xim; }
        else if (mode == 1) {
            perm_swap01<<<(NTOT / 4) / 256, 256>>>((const float4*)s_re, (const float4*)s_im,
                                                   (float4*)u_re, (float4*)u_im);
            cu_re = u_re; cu_im = u_im;
        } else {
            dim3 gt(64 / 32, 16384 / 32, BATCH);
            perm_transpose<<<gt, dim3(32, 8)>>>(s_re, s_im, u_re, u_im, 16384, 64);
            cu_re = u_re; cu_im = u_im;
        }

        // ---- conversions: UT limbs + U limbs + W limbs ----
        conv_ut<<<dim3(rest / 32, d / 32, BATCH), dim3(32, 8)>>>(cu_re, cu_im, utbf, ubf, d, rest);
        conv_limbs_A<<<(d * d + 255) / 256, 256>>>(wre[mode], wim[mode], abf, d * d);

        // ---- NN1 (tensor): l = W * u  -> bf16 limb planes directly ----
        dim3 gnn(rest / 128, d / 64, BATCH);
        tensor_nn<<<gnn, 256, SMEM_TN>>>(abf, 0, utbf, l_re, l_im, lbf, 1, d, rest);

        // ---- NT (tensor split-K): score partials = l * u^T ----
        const int NC = (mode < 2) ? 32 : 64;
        const int KC = rest / NC;               // 256
        dim3 g2(d / 64, d / 64, BATCH * NC);
        tensor_nt<<<g2, 256, SMEM_NT>>>(lbf, ubf, p_re, p_im, d, rest, KC);

        // ---- softmax + phase -> m ----
        const int n = BATCH * d * d;
        softmax_fused<<<BATCH * d, d>>>(p_re, p_im, m_re, m_im, d, n, NC, ltau, sfac);

        // ---- NN2 (tensor): mixed = m * u (fp32 out) ----
        conv_limbs_A<<<(n + 255) / 256, 256>>>(m_re, m_im, abf, n);
        float* o_re = (mode == 0) ? s_re : l_re;
        float* o_im = (mode == 0) ? s_im : l_im;
        tensor_nn<<<gnn, 256, SMEM_TN>>>(abf, d * d, utbf, o_re, o_im, lbf, 0, d, rest);

        // ---- fold back ----
        if (mode == 1) {
            perm_swap01<<<(NTOT / 4) / 256, 256>>>((const float4*)l_re, (const float4*)l_im,
                                                   (float4*)s_re, (float4*)s_im);
        } else if (mode == 2) {
            dim3 gt2(16384 / 32, 64 / 32, BATCH);
            perm_transpose<<<gt2, dim3(32, 8)>>>(l_re, l_im, out_re, out_im, 64, 16384);
        }
    }
}

// round 15
// speedup vs baseline: 1.4482x; 1.0461x over previous
#include <cuda_runtime.h>
#include <cuda_bf16.h>
#include <math.h>

#define BATCH 8
#define SS 1048576              // 128*128*64
#define NTOT (BATCH * SS)       // 8388608 per component
#define ALP 131072              // A-limb plane stride (B*128*128 max)
#define UTP NTOT                // big limb plane stride

// ---------------- scratch (device globals; no allocation) ----------------
__device__ float g_s_re[NTOT];
__device__ float g_s_im[NTOT];
__device__ float g_l_re[NTOT];
__device__ float g_l_im[NTOT];
__device__ float g_p_re[2097152];
__device__ float g_p_im[2097152];
__device__ float g_m_re[131072];
__device__ float g_m_im[131072];
__device__ __nv_bfloat16 g_abf[4 * ALP];   // A limbs: rhi,rlo,ihi,ilo
__device__ __nv_bfloat16 g_utbf[4 * UTP];  // U^T limbs (B,rest,d)
__device__ __nv_bfloat16 g_ubf[4 * UTP];   // U  limbs (B,d,rest)
__device__ __nv_bfloat16 g_lbf[4 * UTP];   // L  limbs (B,d,rest)

typedef unsigned long long u64;

// ---------------- limb helpers --------------------------------------------
__device__ __forceinline__ void limb_split(float x, __nv_bfloat16& h, __nv_bfloat16& l) {
    h = __float2bfloat16(x);
    l = __float2bfloat16(x - __bfloat162float(h));
}

// ================= limb conversion kernels ================================
__global__ void conv_limbs_A(const float* __restrict__ re, const float* __restrict__ im,
                             __nv_bfloat16* __restrict__ out, int n)
{
    int i = blockIdx.x * 256 + threadIdx.x;
    if (i >= n) return;
    __nv_bfloat16 h, l;
    limb_split(re[i], h, l);
    out[0 * ALP + i] = h; out[1 * ALP + i] = l;
    limb_split(im[i], h, l);
    out[2 * ALP + i] = h; out[3 * ALP + i] = l;
}

// mode 0: U (B,d,rest) fp32 -> UT limbs (B,rest,d) AND U limbs (B,d,rest)
__global__ void conv_ut(const float* __restrict__ ure, const float* __restrict__ uim,
                        __nv_bfloat16* __restrict__ outT, __nv_bfloat16* __restrict__ outU,
                        int d, int rest)
{
    __shared__ float tr[32][33], ti[32][33];
    const int b  = blockIdx.z;
    const int k0 = blockIdx.y * 32;
    const int n0 = blockIdx.x * 32;
    const size_t ib = (size_t)b * d * rest;
    const size_t ob = (size_t)b * rest * d;
    const int x = threadIdx.x, y = threadIdx.y;
#pragma unroll
    for (int i = y; i < 32; i += 8) {
        size_t si = ib + (size_t)(k0 + i) * rest + n0 + x;
        float xr = ure[si], xi = uim[si];
        tr[i][x] = xr; ti[i][x] = xi;
        __nv_bfloat16 h, l;
        limb_split(xr, h, l);
        outU[0 * (size_t)UTP + si] = h; outU[1 * (size_t)UTP + si] = l;
        limb_split(xi, h, l);
        outU[2 * (size_t)UTP + si] = h; outU[3 * (size_t)UTP + si] = l;
    }
    __syncthreads();
#pragma unroll
    for (int i = y; i < 32; i += 8) {
        size_t o = ob + (size_t)(n0 + i) * d + k0 + x;
        __nv_bfloat16 h, l;
        limb_split(tr[x][i], h, l);
        outT[0 * (size_t)UTP + o] = h; outT[1 * (size_t)UTP + o] = l;
        limb_split(ti[x][i], h, l);
        outT[2 * (size_t)UTP + o] = h; outT[3 * (size_t)UTP + o] = l;
    }
}

// mode 1 fused unfold+convert: O0 (b,i0,i1,i2) fp32 ->
//   U1 limbs  at (b*128+i1)*16384 + i0*64 + i2   (B,d=128,rest=16384... rest=8192*? = i0*64+i2)
//   UT1 limbs at (b*16384 + i0*64 + i2)*128 + i1
// one (b,i0) slice = 128(i1) x 64(i2); tiles 32x32
__global__ void conv_m1(const float* __restrict__ sre, const float* __restrict__ sim,
                        __nv_bfloat16* __restrict__ outT, __nv_bfloat16* __restrict__ outU)
{
    __shared__ float tr[32][33], ti[32][33];
    const int z  = blockIdx.z;              // b*128 + i0
    const int b  = z >> 7, i0 = z & 127;
    const int r0 = blockIdx.y * 32;         // i1 tile
    const int c0 = blockIdx.x * 32;         // i2 tile
    const int x = threadIdx.x, y = threadIdx.y;
#pragma unroll
    for (int i = y; i < 32; i += 8) {
        size_t si = ((size_t)z * 128 + (r0 + i)) * 64 + c0 + x;
        float xr = sre[si], xi = sim[si];
        tr[i][x] = xr; ti[i][x] = xi;
        // U1 direct write (coalesced over i2)
        size_t uo = ((size_t)b * 128 + (r0 + i)) * 8192 + i0 * 64 + c0 + x;
        __nv_bfloat16 h, l;
        limb_split(xr, h, l);
        outU[0 * (size_t)UTP + uo] = h; outU[1 * (size_t)UTP + uo] = l;
        limb_split(xi, h, l);
        outU[2 * (size_t)UTP + uo] = h; outU[3 * (size_t)UTP + uo] = l;
    }
    __syncthreads();
#pragma unroll
    for (int i = y; i < 32; i += 8) {
        // UT1: row r1 = i0*64 + i2 (i2 = c0+i), col i1 = r0+x (coalesced over i1)
        size_t o = ((size_t)b * 8192 + i0 * 64 + c0 + i) * 128 + r0 + x;
        __nv_bfloat16 h, l;
        limb_split(tr[x][i], h, l);
        outT[0 * (size_t)UTP + o] = h; outT[1 * (size_t)UTP + o] = l;
        limb_split(ti[x][i], h, l);
        outT[2 * (size_t)UTP + o] = h; outT[3 * (size_t)UTP + o] = l;
    }
}

// mode 2 fused (fold1 ∘ unfold2) + convert: O1 (b,i1,i0,i2) fp32 ->
//   U2 limbs  at (b*64+i2)*16384 + i0*128 + i1   (transpose write)
//   UT2 limbs at (b*16384 + i0*128 + i1)*64 + i2 (direct write)
__global__ void conv_m2(const float* __restrict__ sre, const float* __restrict__ sim,
                        __nv_bfloat16* __restrict__ outT, __nv_bfloat16* __restrict__ outU)
{
    __shared__ float tr[32][33], ti[32][33];
    const int z  = blockIdx.z;              // b*128 + i0
    const int b  = z >> 7, i0 = z & 127;
    const int r0 = blockIdx.y * 32;         // i1 tile
    const int c0 = blockIdx.x * 32;         // i2 tile
    const int x = threadIdx.x, y = threadIdx.y;
#pragma unroll
    for (int i = y; i < 32; i += 8) {
        // src O1: ((b*128 + i1)*128 + i0)*64 + i2
        size_t si = (((size_t)b * 128 + (r0 + i)) * 128 + i0) * 64 + c0 + x;
        float xr = sre[si], xi = sim[si];
        tr[i][x] = xr; ti[i][x] = xi;
        // UT2 direct (coalesced over i2)
        size_t o = ((size_t)b * 16384 + i0 * 128 + (r0 + i)) * 64 + c0 + x;
        __nv_bfloat16 h, l;
        limb_split(xr, h, l);
        outT[0 * (size_t)UTP + o] = h; outT[1 * (size_t)UTP + o] = l;
        limb_split(xi, h, l);
        outT[2 * (size_t)UTP + o] = h; outT[3 * (size_t)UTP + o] = l;
    }
    __syncthreads();
#pragma unroll
    for (int i = y; i < 32; i += 8) {
        // U2: row i2 = c0+i, col i0*128 + i1 (i1 = r0+x, coalesced)
        size_t uo = ((size_t)b * 64 + c0 + i) * 16384 + i0 * 128 + r0 + x;
        __nv_bfloat16 h, l;
        limb_split(tr[x][i], h, l);
        outU[0 * (size_t)UTP + uo] = h; outU[1 * (size_t)UTP + uo] = l;
        limb_split(ti[x][i], h, l);
        outU[2 * (size_t)UTP + uo] = h; outU[3 * (size_t)UTP + uo] = l;
    }
}

// ================= mma.sync / cp.async helpers ============================
__device__ __forceinline__ unsigned smem_u32(const void* p) {
    unsigned a;
    asm("{ .reg .u64 t; cvta.to.shared.u64 t, %1; cvt.u32.u64 %0, t; }"
        : "=r"(a) : "l"(p));
    return a;
}
__device__ __forceinline__ void cpasync16(unsigned saddr, const void* g) {
    asm volatile("cp.async.cg.shared.global [%0], [%1], 16;" :: "r"(saddr), "l"(g));
}
#define CP_COMMIT() asm volatile("cp.async.commit_group;" ::: "memory")
#define CP_WAIT0()  asm volatile("cp.async.wait_group 0;" ::: "memory")
__device__ __forceinline__ void ldm_x4(unsigned* r, unsigned addr) {
    asm volatile("ldmatrix.sync.aligned.m8n8.x4.shared.b16 {%0,%1,%2,%3}, [%4];"
                 : "=r"(r[0]), "=r"(r[1]), "=r"(r[2]), "=r"(r[3]) : "r"(addr));
}
__device__ __forceinline__ void mma16816(float* c, const unsigned* a, const unsigned* b) {
    asm volatile(
        "mma.sync.aligned.m16n8k16.row.col.f32.bf16.bf16.f32 "
        "{%0,%1,%2,%3}, {%4,%5,%6,%7}, {%8,%9}, {%0,%1,%2,%3};"
        : "+f"(c[0]), "+f"(c[1]), "+f"(c[2]), "+f"(c[3])
        : "r"(a[0]), "r"(a[1]), "r"(a[2]), "r"(a[3]), "r"(b[0]), "r"(b[1]));
}
__device__ __forceinline__ void wlimb2(__nv_bfloat16* out, size_t idx,
                                       float v0, float v1, int phi, int plo)
{
    __nv_bfloat16 h0, l0, h1, l1;
    limb_split(v0, h0, l0); limb_split(v1, h1, l1);
    unsigned hp = (unsigned)*(unsigned short*)&h0 | ((unsigned)*(unsigned short*)&h1 << 16);
    unsigned lp = (unsigned)*(unsigned short*)&l0 | ((unsigned)*(unsigned short*)&l1 << 16);
    *(unsigned*)(out + (size_t)phi * UTP + idx) = hp;
    *(unsigned*)(out + (size_t)plo * UTP + idx) = lp;
}

#define MMA12(pcr, pci, af, nih, nil_, brh, brl, bih, bil)                   \
    mma16816(pcr, af[0], brh); mma16816(pcr, af[0], brl);                    \
    mma16816(pcr, af[1], brh); mma16816(pcr, nih,   bih);                    \
    mma16816(pcr, nih,   bil); mma16816(pcr, nil_,  bih);                    \
    mma16816(pci, af[0], bih); mma16816(pci, af[0], bil);                    \
    mma16816(pci, af[1], bih); mma16816(pci, af[2], brh);                    \
    mma16816(pci, af[2], brl); mma16816(pci, af[3], brh);

// ================= tensor NN: C[b] = A(b?) * U[b] =========================
#define APITCH 40
#define APL (64 * APITCH)
#define BPL (128 * APITCH)
#define NNBUF (4 * APL + 4 * BPL)
#define SMEM_TN (2 * NNBUF * 2)             // 122880 bytes

__global__ void __launch_bounds__(256, 1)
tensor_nn(const __nv_bfloat16* __restrict__ Ab, int strideAb,
          const __nv_bfloat16* __restrict__ UTb,
          float* __restrict__ Cre, float* __restrict__ Cim,
          __nv_bfloat16* __restrict__ Lbf, int outmode,
          int d, int rest)
{
    extern __shared__ __align__(16) char smem[];
    __nv_bfloat16* buf[2] = { (__nv_bfloat16*)smem, (__nv_bfloat16*)smem + NNBUF };

    const int tid = threadIdx.x, lane = tid & 31, wid = tid >> 5;
    const int b = blockIdx.z, m0 = blockIdx.y * 64, n0 = blockIdx.x * 128;
    const int wm = wid >> 2, wn = wid & 3;

    const int rsel = lane >> 3, l8 = lane & 7;
    const int aro = (rsel & 1) ? 8 : 0, ako = (rsel & 2) ? 8 : 0;
    const int bko = (rsel & 1) ? 8 : 0, bro = (rsel & 2) ? 8 : 0;

    const size_t abase = (size_t)b * strideAb;
    const size_t bbase = (size_t)b * rest * d;

    float cr[2][4][4], ci[2][4][4];
#pragma unroll
    for (int mi = 0; mi < 2; mi++)
#pragma unroll
        for (int ns = 0; ns < 4; ns++)
#pragma unroll
            for (int q = 0; q < 4; q++) { cr[mi][ns][q] = 0.f; ci[mi][ns][q] = 0.f; }

    const int nchunks = d / 32;

#define NN_ISSUE(cc, bx)                                                       \
    {                                                                          \
        __nv_bfloat16* As_ = buf[bx];                                          \
        __nv_bfloat16* Bs_ = buf[bx] + 4 * APL;                                \
        for (int u = tid; u < 1024; u += 256) {                                \
            int p = u >> 8, v = u & 255;                                       \
            int r = v >> 2, j = v & 3;                                         \
            cpasync16(smem_u32(As_ + p * APL + r * APITCH + j * 8),            \
                      Ab + (size_t)p * ALP + abase + (size_t)(m0 + r) * d      \
                      + (cc) * 32 + j * 8);                                    \
        }                                                                      \
        for (int u = tid; u < 2048; u += 256) {                                \
            int p = u >> 9, v = u & 511;                                       \
            int r = v >> 2, j = v & 3;                                         \
            cpasync16(smem_u32(Bs_ + p * BPL + r * APITCH + j * 8),            \
                      UTb + (size_t)p * UTP + bbase + (size_t)(n0 + r) * d     \
                      + (cc) * 32 + j * 8);                                    \
        }                                                                      \
        CP_COMMIT();                                                           \
    }

    NN_ISSUE(0, 0)
    for (int c = 0; c < nchunks; c++) {
        CP_WAIT0();
        __syncthreads();
        if (c + 1 < nchunks) NN_ISSUE(c + 1, (c + 1) & 1)

        __nv_bfloat16* As = buf[c & 1];
        __nv_bfloat16* Bs = buf[c & 1] + 4 * APL;
#pragma unroll
        for (int s = 0; s < 2; s++) {
            unsigned bf[4][2][4];
#pragma unroll
            for (int p = 0; p < 4; p++)
#pragma unroll
                for (int gj = 0; gj < 2; gj++) {
                    unsigned addr = smem_u32(Bs + p * BPL
                        + (wn * 32 + gj * 16 + bro + l8) * APITCH + s * 16 + bko);
                    ldm_x4(bf[p][gj], addr);
                }
#pragma unroll
            for (int mi = 0; mi < 2; mi++) {
                unsigned af[4][4];
#pragma unroll
                for (int p = 0; p < 4; p++) {
                    unsigned addr = smem_u32(As + p * APL
                        + (wm * 32 + mi * 16 + aro + l8) * APITCH + s * 16 + ako);
                    ldm_x4(af[p], addr);
                }
                unsigned nih[4], nil_[4];
#pragma unroll
                for (int q = 0; q < 4; q++) {
                    nih[q]  = af[2][q] ^ 0x80008000u;
                    nil_[q] = af[3][q] ^ 0x80008000u;
                }
#pragma unroll
                for (int ns = 0; ns < 4; ns++) {
                    const unsigned* brh = &bf[0][ns >> 1][(ns & 1) * 2];
                    const unsigned* brl = &bf[1][ns >> 1][(ns & 1) * 2];
                    const unsigned* bih = &bf[2][ns >> 1][(ns & 1) * 2];
                    const unsigned* bil = &bf[3][ns >> 1][(ns & 1) * 2];
                    MMA12(cr[mi][ns], ci[mi][ns], af, nih, nil_, brh, brl, bih, bil)
                }
            }
        }
        __syncthreads();
    }

    const int g = lane >> 2, t = lane & 3;
    const size_t base = (size_t)b * d * rest;
#pragma unroll
    for (int mi = 0; mi < 2; mi++) {
        int mrow = m0 + wm * 32 + mi * 16 + g;
#pragma unroll
        for (int ns = 0; ns < 4; ns++) {
            int col = n0 + wn * 32 + ns * 8 + 2 * t;
            if (outmode == 0) {
                *(float2*)(Cre + base + (size_t)mrow * rest + col) =
                    make_float2(cr[mi][ns][0], cr[mi][ns][1]);
                *(float2*)(Cre + base + (size_t)(mrow + 8) * rest + col) =
                    make_float2(cr[mi][ns][2], cr[mi][ns][3]);
                *(float2*)(Cim + base + (size_t)mrow * rest + col) =
                    make_float2(ci[mi][ns][0], ci[mi][ns][1]);
                *(float2*)(Cim + base + (size_t)(mrow + 8) * rest + col) =
                    make_float2(ci[mi][ns][2], ci[mi][ns][3]);
            } else {
                size_t i0 = base + (size_t)mrow * rest + col;
                size_t i1 = base + (size_t)(mrow + 8) * rest + col;
                wlimb2(Lbf, i0, cr[mi][ns][0], cr[mi][ns][1], 0, 1);
                wlimb2(Lbf, i1, cr[mi][ns][2], cr[mi][ns][3], 0, 1);
                wlimb2(Lbf, i0, ci[mi][ns][0], ci[mi][ns][1], 2, 3);
                wlimb2(Lbf, i1, ci[mi][ns][2], ci[mi][ns][3], 2, 3);
            }
        }
    }
}

// ============ tensor NT split-K: P[chunk][b] = L[b] * U[b]^T ==============
#define NTPL (64 * APITCH)
#define NTBUF (8 * NTPL)
#define SMEM_NT (2 * NTBUF * 2)              // 81920 bytes

__global__ void __launch_bounds__(256, 1)
tensor_nt(const __nv_bfloat16* __restrict__ Lb, const __nv_bfloat16* __restrict__ Ub,
          float* __restrict__ Pre, float* __restrict__ Pim,
          int d, int K, int KC)
{
    extern __shared__ __align__(16) char smem[];
    __nv_bfloat16* buf[2] = { (__nv_bfloat16*)smem, (__nv_bfloat16*)smem + NTBUF };

    const int tid = threadIdx.x, lane = tid & 31, wid = tid >> 5;
    const int bz = blockIdx.z, b = bz & 7, chunk = bz >> 3;
    const int m0 = blockIdx.y * 64, n0 = blockIdx.x * 64;
    const int wm = wid >> 2, wn = wid & 3;

    const int rsel = lane >> 3, l8 = lane & 7;
    const int aro = (rsel & 1) ? 8 : 0, ako = (rsel & 2) ? 8 : 0;
    const int bko = (rsel & 1) ? 8 : 0, bro = (rsel & 2) ? 8 : 0;

    float cr[2][2][4], ci[2][2][4];
#pragma unroll
    for (int mi = 0; mi < 2; mi++)
#pragma unroll
        for (int ns = 0; ns < 2; ns++)
#pragma unroll
            for (int q = 0; q < 4; q++) { cr[mi][ns][q] = 0.f; ci[mi][ns][q] = 0.f; }

    const size_t bb = (size_t)b * d * K;
    const int kbeg = chunk * KC;
    const int nchunks = KC / 32;

#define NT_ISSUE(cc, bx)                                                       \
    {                                                                          \
        __nv_bfloat16* As_ = buf[bx];                                          \
        __nv_bfloat16* Bs_ = buf[bx] + 4 * NTPL;                               \
        const int ko = kbeg + (cc) * 32;                                       \
        for (int u = tid; u < 1024; u += 256) {                                \
            int p = u >> 8, v = u & 255;                                       \
            int r = v >> 2, j = v & 3;                                         \
            cpasync16(smem_u32(As_ + p * NTPL + r * APITCH + j * 8),           \
                      Lb + (size_t)p * UTP + bb + (size_t)(m0 + r) * K + ko + j * 8); \
            cpasync16(smem_u32(Bs_ + p * NTPL + r * APITCH + j * 8),           \
                      Ub + (size_t)p * UTP + bb + (size_t)(n0 + r) * K + ko + j * 8); \
        }                                                                      \
        CP_COMMIT();                                                           \
    }

    NT_ISSUE(0, 0)
    for (int c = 0; c < nchunks; c++) {
        CP_WAIT0();
        __syncthreads();
        if (c + 1 < nchunks) NT_ISSUE(c + 1, (c + 1) & 1)

        __nv_bfloat16* As = buf[c & 1];
        __nv_bfloat16* Bs = buf[c & 1] + 4 * NTPL;
#pragma unroll
        for (int s = 0; s < 2; s++) {
            unsigned bf[4][4];
#pragma unroll
            for (int p = 0; p < 4; p++) {
                unsigned addr = smem_u32(Bs + p * NTPL
                    + (wn * 16 + bro + l8) * APITCH + s * 16 + bko);
                ldm_x4(bf[p], addr);
            }
#pragma unroll
            for (int mi = 0; mi < 2; mi++) {
                unsigned af[4][4];
#pragma unroll
                for (int p = 0; p < 4; p++) {
                    unsigned addr = smem_u32(As + p * NTPL
                        + (wm * 32 + mi * 16 + aro + l8) * APITCH + s * 16 + ako);
                    ldm_x4(af[p], addr);
                }
                unsigned nih[4], nil_[4];
#pragma unroll
                for (int q = 0; q < 4; q++) {
                    nih[q]  = af[2][q] ^ 0x80008000u;
                    nil_[q] = af[3][q] ^ 0x80008000u;
                }
#pragma unroll
                for (int ns = 0; ns < 2; ns++) {
                    const unsigned* brh = &bf[0][ns * 2];
                    const unsigned* brl = &bf[1][ns * 2];
                    const unsigned* bih = &bf[2][ns * 2];
                    const unsigned* bil = &bf[3][ns * 2];
                    MMA12(cr[mi][ns], ci[mi][ns], af, nih, nil_, brh, brl, bih, bil)
                }
            }
        }
        __syncthreads();
    }

    const int g = lane >> 2, t = lane & 3;
    const size_t off = (size_t)(chunk * BATCH + b) * d * d;
#pragma unroll
    for (int mi = 0; mi < 2; mi++) {
        int mrow = m0 + wm * 32 + mi * 16 + g;
#pragma unroll
        for (int ns = 0; ns < 2; ns++) {
            int col = n0 + wn * 16 + ns * 8 + 2 * t;
            *(float2*)(Pre + off + (size_t)mrow * d + col) =
                make_float2(cr[mi][ns][0], cr[mi][ns][1]);
            *(float2*)(Pre + off + (size_t)(mrow + 8) * d + col) =
                make_float2(cr[mi][ns][2], cr[mi][ns][3]);
            *(float2*)(Pim + off + (size_t)mrow * d + col) =
                make_float2(ci[mi][ns][0], ci[mi][ns][1]);
            *(float2*)(Pim + off + (size_t)(mrow + 8) * d + col) =
                make_float2(ci[mi][ns][2], ci[mi][ns][3]);
        }
    }
}

// ---------------- fused split-K reduce + softmax(|s|/scale)*phase ---------
__global__ void softmax_fused(const float* __restrict__ Pre, const float* __restrict__ Pim,
                              float* __restrict__ Mre, float* __restrict__ Mim,
                              int d, int n, int nchunks,
                              const float* __restrict__ logtau, float sfac)
{
    const int row = blockIdx.x;
    const int j   = threadIdx.x;
    const int idx = row * d + j;

    float sr = 0.f, si = 0.f;
    for (int c = 0; c < nchunks; c++) {
        sr += Pre[(size_t)c * n + idx];
        si += Pim[(size_t)c * n + idx];
    }
    const float mag = sqrtf(sr * sr + si * si);

    const float tau   = fmaxf(expf(logtau[0]), 1e-8f);
    const float scale = tau * sfac;
    const float logit = mag / scale;

    __shared__ float wred[4];
    __shared__ float wsum[4];
    const int warp = j >> 5, lane = j & 31, nw = d >> 5;

    float v = logit;
#pragma unroll
    for (int o = 16; o > 0; o >>= 1) v = fmaxf(v, __shfl_xor_sync(0xffffffffu, v, o));
    if (lane == 0) wred[warp] = v;
    __syncthreads();
    float mx = wred[0];
    for (int w = 1; w < nw; w++) mx = fmaxf(mx, wred[w]);

    const float e = expf(logit - mx);
    float s_ = e;
#pragma unroll
    for (int o = 16; o > 0; o >>= 1) s_ += __shfl_xor_sync(0xffffffffu, s_, o);
    if (lane == 0) wsum[warp] = s_;
    __syncthreads();
    float tot = 0.f;
    for (int w = 0; w < nw; w++) tot += wsum[w];

    const float routing = e / tot;
    float pr, pi;
    if (mag > 1e-8f) { pr = sr / mag; pi = si / mag; }
    else             { pr = 1.f;      pi = 0.f; }
    Mre[(size_t)row * d + j] = routing * pr;
    Mim[(size_t)row * d + j] = routing * pi;
}

// ---------------- final fold transpose ------------------------------------
__global__ void perm_transpose(const float* __restrict__ sre, const float* __restrict__ sim,
                               float* __restrict__ dre, float* __restrict__ dim_,
                               int R, int C)
{
    __shared__ float tre[32][33], tim[32][33];
    const int b  = blockIdx.z;
    const int r0 = blockIdx.y * 32;
    const int c0 = blockIdx.x * 32;
    const float* sr_ = sre + (size_t)b * R * C;
    const float* si_ = sim + (size_t)b * R * C;
    float*       dr_ = dre + (size_t)b * R * C;
    float*       di_ = dim_ + (size_t)b * R * C;
    const int x = threadIdx.x, y = threadIdx.y;
#pragma unroll
    for (int i = y; i < 32; i += 8) {
        tre[i][x] = sr_[(size_t)(r0 + i) * C + c0 + x];
        tim[i][x] = si_[(size_t)(r0 + i) * C + c0 + x];
    }
    __syncthreads();
#pragma unroll
    for (int i = y; i < 32; i += 8) {
        dr_[(size_t)(c0 + i) * R + r0 + x] = tre[x][i];
        di_[(size_t)(c0 + i) * R + r0 + x] = tim[x][i];
    }
}

// --------------------------------------------------------------------------
extern "C" void kernel_launch(void* const* d_in, const int* in_sizes, int n_in,
                              void* d_out, int out_size)
{
    (void)in_sizes; (void)n_in; (void)out_size;
    const float* xre  = (const float*)d_in[0];
    const float* xim  = (const float*)d_in[1];
    const float* wre[3] = {(const float*)d_in[2], (const float*)d_in[4], (const float*)d_in[6]};
    const float* wim[3] = {(const float*)d_in[3], (const float*)d_in[5], (const float*)d_in[7]};
    const float* ltau = (const float*)d_in[8];
    float* out_re = (float*)d_out;
    float* out_im = out_re + (size_t)NTOT;

    float *s_re, *s_im, *l_re, *l_im, *p_re, *p_im, *m_re, *m_im;
    __nv_bfloat16 *abf, *utbf, *ubf, *lbf;
    cudaGetSymbolAddress((void**)&s_re,  g_s_re);
    cudaGetSymbolAddress((void**)&s_im,  g_s_im);
    cudaGetSymbolAddress((void**)&l_re,  g_l_re);
    cudaGetSymbolAddress((void**)&l_im,  g_l_im);
    cudaGetSymbolAddress((void**)&p_re,  g_p_re);
    cudaGetSymbolAddress((void**)&p_im,  g_p_im);
    cudaGetSymbolAddress((void**)&m_re,  g_m_re);
    cudaGetSymbolAddress((void**)&m_im,  g_m_im);
    cudaGetSymbolAddress((void**)&abf,   g_abf);
    cudaGetSymbolAddress((void**)&utbf,  g_utbf);
    cudaGetSymbolAddress((void**)&ubf,   g_ubf);
    cudaGetSymbolAddress((void**)&lbf,   g_lbf);

    cudaFuncSetAttribute(tensor_nn, cudaFuncAttributeMaxDynamicSharedMemorySize, SMEM_TN);
    cudaFuncSetAttribute(tensor_nt, cudaFuncAttributeMaxDynamicSharedMemorySize, SMEM_NT);

    for (int mode = 0; mode < 3; mode++) {
        const int d    = (mode < 2) ? 128 : 64;
        const int rest = SS / d;
        const float sfac = sqrtf((float)SS / (float)d);

        // ---- fused unfold + limb conversion (no fp32 permute passes) ----
        if (mode == 0) {
            conv_ut<<<dim3(rest / 32, d / 32, BATCH), dim3(32, 8)>>>(xre, xim, utbf, ubf, d, rest);
        } else if (mode == 1) {
            conv_m1<<<dim3(2, 4, BATCH * 128), dim3(32, 8)>>>(s_re, s_im, utbf, ubf);
        } else {
            conv_m2<<<dim3(2, 4, BATCH * 128), dim3(32, 8)>>>(l_re, l_im, utbf, ubf);
        }
        conv_limbs_A<<<(d * d + 255) / 256, 256>>>(wre[mode], wim[mode], abf, d * d);

        // ---- NN1 (tensor): l = W * u  -> bf16 limb planes directly ----
        dim3 gnn(rest / 128, d / 64, BATCH);
        tensor_nn<<<gnn, 256, SMEM_TN>>>(abf, 0, utbf, l_re, l_im, lbf, 1, d, rest);

        // ---- NT (tensor split-K): score partials = l * u^T ----
        const int NC = (mode < 2) ? 16 : 64;
        const int KC = rest / NC;               // 512 / 256
        dim3 g2(d / 64, d / 64, BATCH * NC);
        tensor_nt<<<g2, 256, SMEM_NT>>>(lbf, ubf, p_re, p_im, d, rest, KC);

        // ---- softmax + phase -> m ----
        const int n = BATCH * d * d;
        softmax_fused<<<BATCH * d, d>>>(p_re, p_im, m_re, m_im, d, n, NC, ltau, sfac);

        // ---- NN2 (tensor): mixed = m * u (fp32 out in mode-m layout) ----
        conv_limbs_A<<<(n + 255) / 256, 256>>>(m_re, m_im, abf, n);
        float* o_re = (mode == 0) ? s_re : l_re;
        float* o_im = (mode == 0) ? s_im : l_im;
        tensor_nn<<<gnn, 256, SMEM_TN>>>(abf, d * d, utbf, o_re, o_im, lbf, 0, d, rest);

        // ---- final fold (mode 2 only): out[b,p,k] = O2[b,k,p] ----
        if (mode == 2) {
            dim3 gt2(16384 / 32, 64 / 32, BATCH);
            perm_transpose<<<gt2, dim3(32, 8)>>>(l_re, l_im, out_re, out_im, 64, 16384);
        }
    }
}

// round 16
// speedup vs baseline: 1.4711x; 1.0158x over previous
#include <cuda_runtime.h>
#include <cuda_bf16.h>
#include <math.h>

#define BATCH 8
#define SS 1048576              // 128*128*64
#define NTOT (BATCH * SS)       // 8388608 per component
#define ALP 131072              // A-limb plane stride (B*128*128 max)
#define UTP NTOT                // big limb plane stride

// ---------------- scratch (device globals; no allocation) ----------------
__device__ float g_s_re[NTOT];
__device__ float g_s_im[NTOT];
__device__ float g_l_re[NTOT];
__device__ float g_l_im[NTOT];
__device__ float g_p_re[2097152];
__device__ float g_p_im[2097152];
__device__ float g_m_re[131072];
__device__ float g_m_im[131072];
__device__ __nv_bfloat16 g_abf[4 * ALP];   // A limbs: rhi,rlo,ihi,ilo
__device__ __nv_bfloat16 g_utbf[4 * UTP];  // U^T limbs (B,rest,d)
__device__ __nv_bfloat16 g_ubf[4 * UTP];   // U  limbs (B,d,rest)
__device__ __nv_bfloat16 g_lbf[4 * UTP];   // L  limbs (B,d,rest)

typedef unsigned long long u64;

// ---------------- limb helpers --------------------------------------------
__device__ __forceinline__ void limb_split(float x, __nv_bfloat16& h, __nv_bfloat16& l) {
    h = __float2bfloat16(x);
    l = __float2bfloat16(x - __bfloat162float(h));
}

// ================= limb conversion kernels ================================
__global__ void conv_limbs_A(const float* __restrict__ re, const float* __restrict__ im,
                             __nv_bfloat16* __restrict__ out, int n)
{
    int i = blockIdx.x * 256 + threadIdx.x;
    if (i >= n) return;
    __nv_bfloat16 h, l;
    limb_split(re[i], h, l);
    out[0 * ALP + i] = h; out[1 * ALP + i] = l;
    limb_split(im[i], h, l);
    out[2 * ALP + i] = h; out[3 * ALP + i] = l;
}

// mode 0: U (B,d,rest) fp32 -> UT limbs (B,rest,d) AND U limbs (B,d,rest)
__global__ void conv_ut(const float* __restrict__ ure, const float* __restrict__ uim,
                        __nv_bfloat16* __restrict__ outT, __nv_bfloat16* __restrict__ outU,
                        int d, int rest)
{
    __shared__ float tr[32][33], ti[32][33];
    const int b  = blockIdx.z;
    const int k0 = blockIdx.y * 32;
    const int n0 = blockIdx.x * 32;
    const size_t ib = (size_t)b * d * rest;
    const size_t ob = (size_t)b * rest * d;
    const int x = threadIdx.x, y = threadIdx.y;
#pragma unroll
    for (int i = y; i < 32; i += 8) {
        size_t si = ib + (size_t)(k0 + i) * rest + n0 + x;
        float xr = ure[si], xi = uim[si];
        tr[i][x] = xr; ti[i][x] = xi;
        __nv_bfloat16 h, l;
        limb_split(xr, h, l);
        outU[0 * (size_t)UTP + si] = h; outU[1 * (size_t)UTP + si] = l;
        limb_split(xi, h, l);
        outU[2 * (size_t)UTP + si] = h; outU[3 * (size_t)UTP + si] = l;
    }
    __syncthreads();
#pragma unroll
    for (int i = y; i < 32; i += 8) {
        size_t o = ob + (size_t)(n0 + i) * d + k0 + x;
        __nv_bfloat16 h, l;
        limb_split(tr[x][i], h, l);
        outT[0 * (size_t)UTP + o] = h; outT[1 * (size_t)UTP + o] = l;
        limb_split(ti[x][i], h, l);
        outT[2 * (size_t)UTP + o] = h; outT[3 * (size_t)UTP + o] = l;
    }
}

// mode 1 fused unfold+convert
__global__ void conv_m1(const float* __restrict__ sre, const float* __restrict__ sim,
                        __nv_bfloat16* __restrict__ outT, __nv_bfloat16* __restrict__ outU)
{
    __shared__ float tr[32][33], ti[32][33];
    const int z  = blockIdx.z;              // b*128 + i0
    const int b  = z >> 7, i0 = z & 127;
    const int r0 = blockIdx.y * 32;         // i1 tile
    const int c0 = blockIdx.x * 32;         // i2 tile
    const int x = threadIdx.x, y = threadIdx.y;
#pragma unroll
    for (int i = y; i < 32; i += 8) {
        size_t si = ((size_t)z * 128 + (r0 + i)) * 64 + c0 + x;
        float xr = sre[si], xi = sim[si];
        tr[i][x] = xr; ti[i][x] = xi;
        size_t uo = ((size_t)b * 128 + (r0 + i)) * 8192 + i0 * 64 + c0 + x;
        __nv_bfloat16 h, l;
        limb_split(xr, h, l);
        outU[0 * (size_t)UTP + uo] = h; outU[1 * (size_t)UTP + uo] = l;
        limb_split(xi, h, l);
        outU[2 * (size_t)UTP + uo] = h; outU[3 * (size_t)UTP + uo] = l;
    }
    __syncthreads();
#pragma unroll
    for (int i = y; i < 32; i += 8) {
        size_t o = ((size_t)b * 8192 + i0 * 64 + c0 + i) * 128 + r0 + x;
        __nv_bfloat16 h, l;
        limb_split(tr[x][i], h, l);
        outT[0 * (size_t)UTP + o] = h; outT[1 * (size_t)UTP + o] = l;
        limb_split(ti[x][i], h, l);
        outT[2 * (size_t)UTP + o] = h; outT[3 * (size_t)UTP + o] = l;
    }
}

// mode 2 fused (fold1 ∘ unfold2) + convert
__global__ void conv_m2(const float* __restrict__ sre, const float* __restrict__ sim,
                        __nv_bfloat16* __restrict__ outT, __nv_bfloat16* __restrict__ outU)
{
    __shared__ float tr[32][33], ti[32][33];
    const int z  = blockIdx.z;              // b*128 + i0
    const int b  = z >> 7, i0 = z & 127;
    const int r0 = blockIdx.y * 32;         // i1 tile
    const int c0 = blockIdx.x * 32;         // i2 tile
    const int x = threadIdx.x, y = threadIdx.y;
#pragma unroll
    for (int i = y; i < 32; i += 8) {
        size_t si = (((size_t)b * 128 + (r0 + i)) * 128 + i0) * 64 + c0 + x;
        float xr = sre[si], xi = sim[si];
        tr[i][x] = xr; ti[i][x] = xi;
        size_t o = ((size_t)b * 16384 + i0 * 128 + (r0 + i)) * 64 + c0 + x;
        __nv_bfloat16 h, l;
        limb_split(xr, h, l);
        outT[0 * (size_t)UTP + o] = h; outT[1 * (size_t)UTP + o] = l;
        limb_split(xi, h, l);
        outT[2 * (size_t)UTP + o] = h; outT[3 * (size_t)UTP + o] = l;
    }
    __syncthreads();
#pragma unroll
    for (int i = y; i < 32; i += 8) {
        size_t uo = ((size_t)b * 64 + c0 + i) * 16384 + i0 * 128 + r0 + x;
        __nv_bfloat16 h, l;
        limb_split(tr[x][i], h, l);
        outU[0 * (size_t)UTP + uo] = h; outU[1 * (size_t)UTP + uo] = l;
        limb_split(ti[x][i], h, l);
        outU[2 * (size_t)UTP + uo] = h; outU[3 * (size_t)UTP + uo] = l;
    }
}

// ================= mma.sync / cp.async helpers ============================
__device__ __forceinline__ unsigned smem_u32(const void* p) {
    unsigned a;
    asm("{ .reg .u64 t; cvta.to.shared.u64 t, %1; cvt.u32.u64 %0, t; }"
        : "=r"(a) : "l"(p));
    return a;
}
__device__ __forceinline__ void cpasync16(unsigned saddr, const void* g) {
    asm volatile("cp.async.cg.shared.global [%0], [%1], 16;" :: "r"(saddr), "l"(g));
}
#define CP_COMMIT() asm volatile("cp.async.commit_group;" ::: "memory")
#define CP_WAIT0()  asm volatile("cp.async.wait_group 0;" ::: "memory")
#define CP_WAIT1()  asm volatile("cp.async.wait_group 1;" ::: "memory")
__device__ __forceinline__ void ldm_x4(unsigned* r, unsigned addr) {
    asm volatile("ldmatrix.sync.aligned.m8n8.x4.shared.b16 {%0,%1,%2,%3}, [%4];"
                 : "=r"(r[0]), "=r"(r[1]), "=r"(r[2]), "=r"(r[3]) : "r"(addr));
}
__device__ __forceinline__ void mma16816(float* c, const unsigned* a, const unsigned* b) {
    asm volatile(
        "mma.sync.aligned.m16n8k16.row.col.f32.bf16.bf16.f32 "
        "{%0,%1,%2,%3}, {%4,%5,%6,%7}, {%8,%9}, {%0,%1,%2,%3};"
        : "+f"(c[0]), "+f"(c[1]), "+f"(c[2]), "+f"(c[3])
        : "r"(a[0]), "r"(a[1]), "r"(a[2]), "r"(a[3]), "r"(b[0]), "r"(b[1]));
}
__device__ __forceinline__ void wlimb2(__nv_bfloat16* out, size_t idx,
                                       float v0, float v1, int phi, int plo)
{
    __nv_bfloat16 h0, l0, h1, l1;
    limb_split(v0, h0, l0); limb_split(v1, h1, l1);
    unsigned hp = (unsigned)*(unsigned short*)&h0 | ((unsigned)*(unsigned short*)&h1 << 16);
    unsigned lp = (unsigned)*(unsigned short*)&l0 | ((unsigned)*(unsigned short*)&l1 << 16);
    *(unsigned*)(out + (size_t)phi * UTP + idx) = hp;
    *(unsigned*)(out + (size_t)plo * UTP + idx) = lp;
}

#define MMA12(pcr, pci, af, nih, nil_, brh, brl, bih, bil)                   \
    mma16816(pcr, af[0], brh); mma16816(pcr, af[0], brl);                    \
    mma16816(pcr, af[1], brh); mma16816(pcr, nih,   bih);                    \
    mma16816(pcr, nih,   bil); mma16816(pcr, nil_,  bih);                    \
    mma16816(pci, af[0], bih); mma16816(pci, af[0], bil);                    \
    mma16816(pci, af[1], bih); mma16816(pci, af[2], brh);                    \
    mma16816(pci, af[2], brl); mma16816(pci, af[3], brh);

// shared 64x128 compute body (As 4x64 rows, Bs 4x128 rows, APITCH pitch)
#define BODY_64x128(As, Bs)                                                    \
    for (int s = 0; s < 2; s++) {                                              \
        unsigned bf[4][2][4];                                                  \
        for (int p = 0; p < 4; p++)                                            \
            for (int gj = 0; gj < 2; gj++) {                                   \
                unsigned addr = smem_u32(Bs + p * BPL                          \
                    + (wn * 32 + gj * 16 + bro + l8) * APITCH + s * 16 + bko); \
                ldm_x4(bf[p][gj], addr);                                       \
            }                                                                  \
        for (int mi = 0; mi < 2; mi++) {                                       \
            unsigned af[4][4];                                                 \
            for (int p = 0; p < 4; p++) {                                      \
                unsigned addr = smem_u32(As + p * APL                          \
                    + (wm * 32 + mi * 16 + aro + l8) * APITCH + s * 16 + ako); \
                ldm_x4(af[p], addr);                                           \
            }                                                                  \
            unsigned nih[4], nil_[4];                                          \
            for (int q = 0; q < 4; q++) {                                      \
                nih[q]  = af[2][q] ^ 0x80008000u;                              \
                nil_[q] = af[3][q] ^ 0x80008000u;                              \
            }                                                                  \
            for (int ns = 0; ns < 4; ns++) {                                   \
                const unsigned* brh = &bf[0][ns >> 1][(ns & 1) * 2];           \
                const unsigned* brl = &bf[1][ns >> 1][(ns & 1) * 2];           \
                const unsigned* bih = &bf[2][ns >> 1][(ns & 1) * 2];           \
                const unsigned* bil = &bf[3][ns >> 1][(ns & 1) * 2];           \
                MMA12(cr[mi][ns], ci[mi][ns], af, nih, nil_, brh, brl, bih, bil) \
            }                                                                  \
        }                                                                      \
    }

// ================= tensor NN: C[b] = A(b?) * U[b] =========================
// 3-stage cp.async pipeline; CTA 64x128, 8 warps (2m x 4n)
#define APITCH 40
#define APL (64 * APITCH)
#define BPL (128 * APITCH)
#define NNBUF (4 * APL + 4 * BPL)
#define SMEM_TN (3 * NNBUF * 2)             // 184320 bytes

__global__ void __launch_bounds__(256, 1)
tensor_nn(const __nv_bfloat16* __restrict__ Ab, int strideAb,
          const __nv_bfloat16* __restrict__ UTb,
          float* __restrict__ Cre, float* __restrict__ Cim,
          __nv_bfloat16* __restrict__ Lbf, int outmode,
          int d, int rest)
{
    extern __shared__ __align__(16) char smem[];
    __nv_bfloat16* bufs = (__nv_bfloat16*)smem;

    const int tid = threadIdx.x, lane = tid & 31, wid = tid >> 5;
    const int b = blockIdx.z, m0 = blockIdx.y * 64, n0 = blockIdx.x * 128;
    const int wm = wid >> 2, wn = wid & 3;

    const int rsel = lane >> 3, l8 = lane & 7;
    const int aro = (rsel & 1) ? 8 : 0, ako = (rsel & 2) ? 8 : 0;
    const int bko = (rsel & 1) ? 8 : 0, bro = (rsel & 2) ? 8 : 0;

    const size_t abase = (size_t)b * strideAb;
    const size_t bbase = (size_t)b * rest * d;

    float cr[2][4][4], ci[2][4][4];
#pragma unroll
    for (int mi = 0; mi < 2; mi++)
#pragma unroll
        for (int ns = 0; ns < 4; ns++)
#pragma unroll
            for (int q = 0; q < 4; q++) { cr[mi][ns][q] = 0.f; ci[mi][ns][q] = 0.f; }

    const int nchunks = d / 32;

#define NN_ISSUE(cc)                                                           \
    {                                                                          \
        __nv_bfloat16* As_ = bufs + ((cc) % 3) * NNBUF;                        \
        __nv_bfloat16* Bs_ = As_ + 4 * APL;                                    \
        for (int u = tid; u < 1024; u += 256) {                                \
            int p = u >> 8, v = u & 255;                                       \
            int r = v >> 2, j = v & 3;                                         \
            cpasync16(smem_u32(As_ + p * APL + r * APITCH + j * 8),            \
                      Ab + (size_t)p * ALP + abase + (size_t)(m0 + r) * d      \
                      + (cc) * 32 + j * 8);                                    \
        }                                                                      \
        for (int u = tid; u < 2048; u += 256) {                                \
            int p = u >> 9, v = u & 511;                                       \
            int r = v >> 2, j = v & 3;                                         \
            cpasync16(smem_u32(Bs_ + p * BPL + r * APITCH + j * 8),            \
                      UTb + (size_t)p * UTP + bbase + (size_t)(n0 + r) * d     \
                      + (cc) * 32 + j * 8);                                    \
        }                                                                      \
        CP_COMMIT();                                                           \
    }

    NN_ISSUE(0)
    if (nchunks > 1) NN_ISSUE(1)
    for (int c = 0; c < nchunks; c++) {
        if (c + 1 < nchunks) CP_WAIT1(); else CP_WAIT0();
        __syncthreads();
        if (c + 2 < nchunks) NN_ISSUE(c + 2)

        __nv_bfloat16* As = bufs + (c % 3) * NNBUF;
        __nv_bfloat16* Bs = As + 4 * APL;
#pragma unroll
        BODY_64x128(As, Bs)
        __syncthreads();
    }

    const int g = lane >> 2, t = lane & 3;
    const size_t base = (size_t)b * d * rest;
#pragma unroll
    for (int mi = 0; mi < 2; mi++) {
        int mrow = m0 + wm * 32 + mi * 16 + g;
#pragma unroll
        for (int ns = 0; ns < 4; ns++) {
            int col = n0 + wn * 32 + ns * 8 + 2 * t;
            if (outmode == 0) {
                *(float2*)(Cre + base + (size_t)mrow * rest + col) =
                    make_float2(cr[mi][ns][0], cr[mi][ns][1]);
                *(float2*)(Cre + base + (size_t)(mrow + 8) * rest + col) =
                    make_float2(cr[mi][ns][2], cr[mi][ns][3]);
                *(float2*)(Cim + base + (size_t)mrow * rest + col) =
                    make_float2(ci[mi][ns][0], ci[mi][ns][1]);
                *(float2*)(Cim + base + (size_t)(mrow + 8) * rest + col) =
                    make_float2(ci[mi][ns][2], ci[mi][ns][3]);
            } else {
                size_t i0 = base + (size_t)mrow * rest + col;
                size_t i1 = base + (size_t)(mrow + 8) * rest + col;
                wlimb2(Lbf, i0, cr[mi][ns][0], cr[mi][ns][1], 0, 1);
                wlimb2(Lbf, i1, cr[mi][ns][2], cr[mi][ns][3], 0, 1);
                wlimb2(Lbf, i0, ci[mi][ns][0], ci[mi][ns][1], 2, 3);
                wlimb2(Lbf, i1, ci[mi][ns][2], ci[mi][ns][3], 2, 3);
            }
        }
    }
}

// ====== tensor NT wide (modes 0/1, d=128): CTA 64(M) x 128(N) =============
// P[chunk][b][m][n] = sum_{k in chunk} L[b][m][k] * U[b][n][k]
#define SMEM_NTW (3 * NNBUF * 2)            // 184320 bytes

__global__ void __launch_bounds__(256, 1)
tensor_nt_wide(const __nv_bfloat16* __restrict__ Lb, const __nv_bfloat16* __restrict__ Ub,
               float* __restrict__ Pre, float* __restrict__ Pim,
               int d, int K, int KC)
{
    extern __shared__ __align__(16) char smem[];
    __nv_bfloat16* bufs = (__nv_bfloat16*)smem;

    const int tid = threadIdx.x, lane = tid & 31, wid = tid >> 5;
    const int bz = blockIdx.z, b = bz & 7, chunk = bz >> 3;
    const int m0 = blockIdx.y * 64, n0 = blockIdx.x * 128;
    const int wm = wid >> 2, wn = wid & 3;

    const int rsel = lane >> 3, l8 = lane & 7;
    const int aro = (rsel & 1) ? 8 : 0, ako = (rsel & 2) ? 8 : 0;
    const int bko = (rsel & 1) ? 8 : 0, bro = (rsel & 2) ? 8 : 0;

    const size_t bb = (size_t)b * d * K;
    const int kbeg = chunk * KC;

    float cr[2][4][4], ci[2][4][4];
#pragma unroll
    for (int mi = 0; mi < 2; mi++)
#pragma unroll
        for (int ns = 0; ns < 4; ns++)
#pragma unroll
            for (int q = 0; q < 4; q++) { cr[mi][ns][q] = 0.f; ci[mi][ns][q] = 0.f; }

    const int nchunks = KC / 32;

#define NTW_ISSUE(cc)                                                          \
    {                                                                          \
        __nv_bfloat16* As_ = bufs + ((cc) % 3) * NNBUF;                        \
        __nv_bfloat16* Bs_ = As_ + 4 * APL;                                    \
        const int ko = kbeg + (cc) * 32;                                       \
        for (int u = tid; u < 1024; u += 256) {                                \
            int p = u >> 8, v = u & 255;                                       \
            int r = v >> 2, j = v & 3;                                         \
            cpasync16(smem_u32(As_ + p * APL + r * APITCH + j * 8),            \
                      Lb + (size_t)p * UTP + bb + (size_t)(m0 + r) * K + ko + j * 8); \
        }                                                                      \
        for (int u = tid; u < 2048; u += 256) {                                \
            int p = u >> 9, v = u & 511;                                       \
            int r = v >> 2, j = v & 3;                                         \
            cpasync16(smem_u32(Bs_ + p * BPL + r * APITCH + j * 8),            \
                      Ub + (size_t)p * UTP + bb + (size_t)(n0 + r) * K + ko + j * 8); \
        }                                                                      \
        CP_COMMIT();                                                           \
    }

    NTW_ISSUE(0)
    if (nchunks > 1) NTW_ISSUE(1)
    for (int c = 0; c < nchunks; c++) {
        if (c + 1 < nchunks) CP_WAIT1(); else CP_WAIT0();
        __syncthreads();
        if (c + 2 < nchunks) NTW_ISSUE(c + 2)

        __nv_bfloat16* As = bufs + (c % 3) * NNBUF;
        __nv_bfloat16* Bs = As + 4 * APL;
#pragma unroll
        BODY_64x128(As, Bs)
        __syncthreads();
    }

    const int g = lane >> 2, t = lane & 3;
    const size_t off = (size_t)(chunk * BATCH + b) * d * d;
#pragma unroll
    for (int mi = 0; mi < 2; mi++) {
        int mrow = m0 + wm * 32 + mi * 16 + g;
#pragma unroll
        for (int ns = 0; ns < 4; ns++) {
            int col = n0 + wn * 32 + ns * 8 + 2 * t;
            *(float2*)(Pre + off + (size_t)mrow * d + col) =
                make_float2(cr[mi][ns][0], cr[mi][ns][1]);
            *(float2*)(Pre + off + (size_t)(mrow + 8) * d + col) =
                make_float2(cr[mi][ns][2], cr[mi][ns][3]);
            *(float2*)(Pim + off + (size_t)mrow * d + col) =
                make_float2(ci[mi][ns][0], ci[mi][ns][1]);
            *(float2*)(Pim + off + (size_t)(mrow + 8) * d + col) =
                make_float2(ci[mi][ns][2], ci[mi][ns][3]);
        }
    }
}

// ============ tensor NT 64x64 (mode 2, d=64) — 2-stage (proven) ===========
#define NTPL (64 * APITCH)
#define NTBUF (8 * NTPL)
#define SMEM_NT (2 * NTBUF * 2)              // 81920 bytes

__global__ void __launch_bounds__(256, 1)
tensor_nt(const __nv_bfloat16* __restrict__ Lb, const __nv_bfloat16* __restrict__ Ub,
          float* __restrict__ Pre, float* __restrict__ Pim,
          int d, int K, int KC)
{
    extern __shared__ __align__(16) char smem[];
    __nv_bfloat16* buf[2] = { (__nv_bfloat16*)smem, (__nv_bfloat16*)smem + NTBUF };

    const int tid = threadIdx.x, lane = tid & 31, wid = tid >> 5;
    const int bz = blockIdx.z, b = bz & 7, chunk = bz >> 3;
    const int m0 = blockIdx.y * 64, n0 = blockIdx.x * 64;
    const int wm = wid >> 2, wn = wid & 3;

    const int rsel = lane >> 3, l8 = lane & 7;
    const int aro = (rsel & 1) ? 8 : 0, ako = (rsel & 2) ? 8 : 0;
    const int bko = (rsel & 1) ? 8 : 0, bro = (rsel & 2) ? 8 : 0;

    float cr[2][2][4], ci[2][2][4];
#pragma unroll
    for (int mi = 0; mi < 2; mi++)
#pragma unroll
        for (int ns = 0; ns < 2; ns++)
#pragma unroll
            for (int q = 0; q < 4; q++) { cr[mi][ns][q] = 0.f; ci[mi][ns][q] = 0.f; }

    const size_t bb = (size_t)b * d * K;
    const int kbeg = chunk * KC;
    const int nchunks = KC / 32;

#define NT_ISSUE(cc, bx)                                                       \
    {                                                                          \
        __nv_bfloat16* As_ = buf[bx];                                          \
        __nv_bfloat16* Bs_ = buf[bx] + 4 * NTPL;                               \
        const int ko = kbeg + (cc) * 32;                                       \
        for (int u = tid; u < 1024; u += 256) {                                \
            int p = u >> 8, v = u & 255;                                       \
            int r = v >> 2, j = v & 3;                                         \
            cpasync16(smem_u32(As_ + p * NTPL + r * APITCH + j * 8),           \
                      Lb + (size_t)p * UTP + bb + (size_t)(m0 + r) * K + ko + j * 8); \
            cpasync16(smem_u32(Bs_ + p * NTPL + r * APITCH + j * 8),           \
                      Ub + (size_t)p * UTP + bb + (size_t)(n0 + r) * K + ko + j * 8); \
        }                                                                      \
        CP_COMMIT();                                                           \
    }

    NT_ISSUE(0, 0)
    for (int c = 0; c < nchunks; c++) {
        CP_WAIT0();
        __syncthreads();
        if (c + 1 < nchunks) NT_ISSUE(c + 1, (c + 1) & 1)

        __nv_bfloat16* As = buf[c & 1];
        __nv_bfloat16* Bs = buf[c & 1] + 4 * NTPL;
#pragma unroll
        for (int s = 0; s < 2; s++) {
            unsigned bf[4][4];
#pragma unroll
            for (int p = 0; p < 4; p++) {
                unsigned addr = smem_u32(Bs + p * NTPL
                    + (wn * 16 + bro + l8) * APITCH + s * 16 + bko);
                ldm_x4(bf[p], addr);
            }
#pragma unroll
            for (int mi = 0; mi < 2; mi++) {
                unsigned af[4][4];
#pragma unroll
                for (int p = 0; p < 4; p++) {
                    unsigned addr = smem_u32(As + p * NTPL
                        + (wm * 32 + mi * 16 + aro + l8) * APITCH + s * 16 + ako);
                    ldm_x4(af[p], addr);
                }
                unsigned nih[4], nil_[4];
#pragma unroll
                for (int q = 0; q < 4; q++) {
                    nih[q]  = af[2][q] ^ 0x80008000u;
                    nil_[q] = af[3][q] ^ 0x80008000u;
                }
#pragma unroll
                for (int ns = 0; ns < 2; ns++) {
                    const unsigned* brh = &bf[0][ns * 2];
                    const unsigned* brl = &bf[1][ns * 2];
                    const unsigned* bih = &bf[2][ns * 2];
                    const unsigned* bil = &bf[3][ns * 2];
                    MMA12(cr[mi][ns], ci[mi][ns], af, nih, nil_, brh, brl, bih, bil)
                }
            }
        }
        __syncthreads();
    }

    const int g = lane >> 2, t = lane & 3;
    const size_t off = (size_t)(chunk * BATCH + b) * d * d;
#pragma unroll
    for (int mi = 0; mi < 2; mi++) {
        int mrow = m0 + wm * 32 + mi * 16 + g;
#pragma unroll
        for (int ns = 0; ns < 2; ns++) {
            int col = n0 + wn * 16 + ns * 8 + 2 * t;
            *(float2*)(Pre + off + (size_t)mrow * d + col) =
                make_float2(cr[mi][ns][0], cr[mi][ns][1]);
            *(float2*)(Pre + off + (size_t)(mrow + 8) * d + col) =
                make_float2(cr[mi][ns][2], cr[mi][ns][3]);
            *(float2*)(Pim + off + (size_t)mrow * d + col) =
                make_float2(ci[mi][ns][0], ci[mi][ns][1]);
            *(float2*)(Pim + off + (size_t)(mrow + 8) * d + col) =
                make_float2(ci[mi][ns][2], ci[mi][ns][3]);
        }
    }
}

// ---------------- fused split-K reduce + softmax(|s|/scale)*phase ---------
__global__ void softmax_fused(const float* __restrict__ Pre, const float* __restrict__ Pim,
                              float* __restrict__ Mre, float* __restrict__ Mim,
                              int d, int n, int nchunks,
                              const float* __restrict__ logtau, float sfac)
{
    const int row = blockIdx.x;
    const int j   = threadIdx.x;
    const int idx = row * d + j;

    float sr = 0.f, si = 0.f;
    for (int c = 0; c < nchunks; c++) {
        sr += Pre[(size_t)c * n + idx];
        si += Pim[(size_t)c * n + idx];
    }
    const float mag = sqrtf(sr * sr + si * si);

    const float tau   = fmaxf(expf(logtau[0]), 1e-8f);
    const float scale = tau * sfac;
    const float logit = mag / scale;

    __shared__ float wred[4];
    __shared__ float wsum[4];
    const int warp = j >> 5, lane = j & 31, nw = d >> 5;

    float v = logit;
#pragma unroll
    for (int o = 16; o > 0; o >>= 1) v = fmaxf(v, __shfl_xor_sync(0xffffffffu, v, o));
    if (lane == 0) wred[warp] = v;
    __syncthreads();
    float mx = wred[0];
    for (int w = 1; w < nw; w++) mx = fmaxf(mx, wred[w]);

    const float e = expf(logit - mx);
    float s_ = e;
#pragma unroll
    for (int o = 16; o > 0; o >>= 1) s_ += __shfl_xor_sync(0xffffffffu, s_, o);
    if (lane == 0) wsum[warp] = s_;
    __syncthreads();
    float tot = 0.f;
    for (int w = 0; w < nw; w++) tot += wsum[w];

    const float routing = e / tot;
    float pr, pi;
    if (mag > 1e-8f) { pr = sr / mag; pi = si / mag; }
    else             { pr = 1.f;      pi = 0.f; }
    Mre[(size_t)row * d + j] = routing * pr;
    Mim[(size_t)row * d + j] = routing * pi;
}

// ---------------- final fold transpose ------------------------------------
__global__ void perm_transpose(const float* __restrict__ sre, const float* __restrict__ sim,
                               float* __restrict__ dre, float* __restrict__ dim_,
                               int R, int C)
{
    __shared__ float tre[32][33], tim[32][33];
    const int b  = blockIdx.z;
    const int r0 = blockIdx.y * 32;
    const int c0 = blockIdx.x * 32;
    const float* sr_ = sre + (size_t)b * R * C;
    const float* si_ = sim + (size_t)b * R * C;
    float*       dr_ = dre + (size_t)b * R * C;
    float*       di_ = dim_ + (size_t)b * R * C;
    const int x = threadIdx.x, y = threadIdx.y;
#pragma unroll
    for (int i = y; i < 32; i += 8) {
        tre[i][x] = sr_[(size_t)(r0 + i) * C + c0 + x];
        tim[i][x] = si_[(size_t)(r0 + i) * C + c0 + x];
    }
    __syncthreads();
#pragma unroll
    for (int i = y; i < 32; i += 8) {
        dr_[(size_t)(c0 + i) * R + r0 + x] = tre[x][i];
        di_[(size_t)(c0 + i) * R + r0 + x] = tim[x][i];
    }
}

// --------------------------------------------------------------------------
extern "C" void kernel_launch(void* const* d_in, const int* in_sizes, int n_in,
                              void* d_out, int out_size)
{
    (void)in_sizes; (void)n_in; (void)out_size;
    const float* xre  = (const float*)d_in[0];
    const float* xim  = (const float*)d_in[1];
    const float* wre[3] = {(const float*)d_in[2], (const float*)d_in[4], (const float*)d_in[6]};
    const float* wim[3] = {(const float*)d_in[3], (const float*)d_in[5], (const float*)d_in[7]};
    const float* ltau = (const float*)d_in[8];
    float* out_re = (float*)d_out;
    float* out_im = out_re + (size_t)NTOT;

    float *s_re, *s_im, *l_re, *l_im, *p_re, *p_im, *m_re, *m_im;
    __nv_bfloat16 *abf, *utbf, *ubf, *lbf;
    cudaGetSymbolAddress((void**)&s_re,  g_s_re);
    cudaGetSymbolAddress((void**)&s_im,  g_s_im);
    cudaGetSymbolAddress((void**)&l_re,  g_l_re);
    cudaGetSymbolAddress((void**)&l_im,  g_l_im);
    cudaGetSymbolAddress((void**)&p_re,  g_p_re);
    cudaGetSymbolAddress((void**)&p_im,  g_p_im);
    cudaGetSymbolAddress((void**)&m_re,  g_m_re);
    cudaGetSymbolAddress((void**)&m_im,  g_m_im);
    cudaGetSymbolAddress((void**)&abf,   g_abf);
    cudaGetSymbolAddress((void**)&utbf,  g_utbf);
    cudaGetSymbolAddress((void**)&ubf,   g_ubf);
    cudaGetSymbolAddress((void**)&lbf,   g_lbf);

    cudaFuncSetAttribute(tensor_nn, cudaFuncAttributeMaxDynamicSharedMemorySize, SMEM_TN);
    cudaFuncSetAttribute(tensor_nt_wide, cudaFuncAttributeMaxDynamicSharedMemorySize, SMEM_NTW);
    cudaFuncSetAttribute(tensor_nt, cudaFuncAttributeMaxDynamicSharedMemorySize, SMEM_NT);

    for (int mode = 0; mode < 3; mode++) {
        const int d    = (mode < 2) ? 128 : 64;
        const int rest = SS / d;
        const float sfac = sqrtf((float)SS / (float)d);

        // ---- fused unfold + limb conversion ----
        if (mode == 0) {
            conv_ut<<<dim3(rest / 32, d / 32, BATCH), dim3(32, 8)>>>(xre, xim, utbf, ubf, d, rest);
        } else if (mode == 1) {
            conv_m1<<<dim3(2, 4, BATCH * 128), dim3(32, 8)>>>(s_re, s_im, utbf, ubf);
        } else {
            conv_m2<<<dim3(2, 4, BATCH * 128), dim3(32, 8)>>>(l_re, l_im, utbf, ubf);
        }
        conv_limbs_A<<<(d * d + 255) / 256, 256>>>(wre[mode], wim[mode], abf, d * d);

        // ---- NN1 (tensor): l = W * u  -> bf16 limb planes directly ----
        dim3 gnn(rest / 128, d / 64, BATCH);
        tensor_nn<<<gnn, 256, SMEM_TN>>>(abf, 0, utbf, l_re, l_im, lbf, 1, d, rest);

        // ---- NT (tensor split-K): score partials = l * u^T ----
        const int NC = (mode < 2) ? 16 : 64;
        const int KC = rest / NC;               // 512 / 256
        if (mode < 2) {
            dim3 g2(d / 128, d / 64, BATCH * NC);
            tensor_nt_wide<<<g2, 256, SMEM_NTW>>>(lbf, ubf, p_re, p_im, d, rest, KC);
        } else {
            dim3 g2(d / 64, d / 64, BATCH * NC);
            tensor_nt<<<g2, 256, SMEM_NT>>>(lbf, ubf, p_re, p_im, d, rest, KC);
        }

        // ---- softmax + phase -> m ----
        const int n = BATCH * d * d;
        softmax_fused<<<BATCH * d, d>>>(p_re, p_im, m_re, m_im, d, n, NC, ltau, sfac);

        // ---- NN2 (tensor): mixed = m * u (fp32 out in mode-m layout) ----
        conv_limbs_A<<<(n + 255) / 256, 256>>>(m_re, m_im, abf, n);
        float* o_re = (mode == 0) ? s_re : l_re;
        float* o_im = (mode == 0) ? s_im : l_im;
        tensor_nn<<<gnn, 256, SMEM_TN>>>(abf, d * d, utbf, o_re, o_im, lbf, 0, d, rest);

        // ---- final fold (mode 2 only): out[b,p,k] = O2[b,k,p] ----
        if (mode == 2) {
            dim3 gt2(16384 / 32, 64 / 32, BATCH);
            perm_transpose<<<gt2, dim3(32, 8)>>>(l_re, l_im, out_re, out_im, 64, 16384);
        }
    }
}

// round 17
// speedup vs baseline: 1.4898x; 1.0127x over previous
#include <cuda_runtime.h>
#include <cuda_bf16.h>
#include <math.h>

#define BATCH 8
#define SS 1048576              // 128*128*64
#define NTOT (BATCH * SS)       // 8388608 per component
#define ALP 131072              // A-limb plane stride (B*128*128 max)
#define UTP NTOT                // big limb plane stride

// ---------------- scratch (device globals; no allocation) ----------------
__device__ float g_s_re[NTOT];
__device__ float g_s_im[NTOT];
__device__ float g_l_re[NTOT];
__device__ float g_l_im[NTOT];
__device__ float g_p_re[4194304];
__device__ float g_p_im[4194304];
__device__ float g_m_re[131072];
__device__ float g_m_im[131072];
__device__ __nv_bfloat16 g_abf[4 * ALP];   // A limbs: rhi,rlo,ihi,ilo
__device__ __nv_bfloat16 g_utbf[4 * UTP];  // U^T limbs (B,rest,d)
__device__ __nv_bfloat16 g_ubf[4 * UTP];   // U  limbs (B,d,rest)
__device__ __nv_bfloat16 g_lbf[4 * UTP];   // L  limbs (B,d,rest)

typedef unsigned long long u64;

// ---------------- limb helpers --------------------------------------------
__device__ __forceinline__ void limb_split(float x, __nv_bfloat16& h, __nv_bfloat16& l) {
    h = __float2bfloat16(x);
    l = __float2bfloat16(x - __bfloat162float(h));
}

// ================= limb conversion kernels ================================
__global__ void conv_limbs_A(const float* __restrict__ re, const float* __restrict__ im,
                             __nv_bfloat16* __restrict__ out, int n)
{
    int i = blockIdx.x * 256 + threadIdx.x;
    if (i >= n) return;
    __nv_bfloat16 h, l;
    limb_split(re[i], h, l);
    out[0 * ALP + i] = h; out[1 * ALP + i] = l;
    limb_split(im[i], h, l);
    out[2 * ALP + i] = h; out[3 * ALP + i] = l;
}

// mode 0: U (B,d,rest) fp32 -> UT limbs (B,rest,d) AND U limbs (B,d,rest)
__global__ void conv_ut(const float* __restrict__ ure, const float* __restrict__ uim,
                        __nv_bfloat16* __restrict__ outT, __nv_bfloat16* __restrict__ outU,
                        int d, int rest)
{
    __shared__ float tr[32][33], ti[32][33];
    const int b  = blockIdx.z;
    const int k0 = blockIdx.y * 32;
    const int n0 = blockIdx.x * 32;
    const size_t ib = (size_t)b * d * rest;
    const size_t ob = (size_t)b * rest * d;
    const int x = threadIdx.x, y = threadIdx.y;
#pragma unroll
    for (int i = y; i < 32; i += 8) {
        size_t si = ib + (size_t)(k0 + i) * rest + n0 + x;
        float xr = ure[si], xi = uim[si];
        tr[i][x] = xr; ti[i][x] = xi;
        __nv_bfloat16 h, l;
        limb_split(xr, h, l);
        outU[0 * (size_t)UTP + si] = h; outU[1 * (size_t)UTP + si] = l;
        limb_split(xi, h, l);
        outU[2 * (size_t)UTP + si] = h; outU[3 * (size_t)UTP + si] = l;
    }
    __syncthreads();
#pragma unroll
    for (int i = y; i < 32; i += 8) {
        size_t o = ob + (size_t)(n0 + i) * d + k0 + x;
        __nv_bfloat16 h, l;
        limb_split(tr[x][i], h, l);
        outT[0 * (size_t)UTP + o] = h; outT[1 * (size_t)UTP + o] = l;
        limb_split(ti[x][i], h, l);
        outT[2 * (size_t)UTP + o] = h; outT[3 * (size_t)UTP + o] = l;
    }
}

// mode 1 fused unfold+convert
__global__ void conv_m1(const float* __restrict__ sre, const float* __restrict__ sim,
                        __nv_bfloat16* __restrict__ outT, __nv_bfloat16* __restrict__ outU)
{
    __shared__ float tr[32][33], ti[32][33];
    const int z  = blockIdx.z;              // b*128 + i0
    const int b  = z >> 7, i0 = z & 127;
    const int r0 = blockIdx.y * 32;         // i1 tile
    const int c0 = blockIdx.x * 32;         // i2 tile
    const int x = threadIdx.x, y = threadIdx.y;
#pragma unroll
    for (int i = y; i < 32; i += 8) {
        size_t si = ((size_t)z * 128 + (r0 + i)) * 64 + c0 + x;
        float xr = sre[si], xi = sim[si];
        tr[i][x] = xr; ti[i][x] = xi;
        size_t uo = ((size_t)b * 128 + (r0 + i)) * 8192 + i0 * 64 + c0 + x;
        __nv_bfloat16 h, l;
        limb_split(xr, h, l);
        outU[0 * (size_t)UTP + uo] = h; outU[1 * (size_t)UTP + uo] = l;
        limb_split(xi, h, l);
        outU[2 * (size_t)UTP + uo] = h; outU[3 * (size_t)UTP + uo] = l;
    }
    __syncthreads();
#pragma unroll
    for (int i = y; i < 32; i += 8) {
        size_t o = ((size_t)b * 8192 + i0 * 64 + c0 + i) * 128 + r0 + x;
        __nv_bfloat16 h, l;
        limb_split(tr[x][i], h, l);
        outT[0 * (size_t)UTP + o] = h; outT[1 * (size_t)UTP + o] = l;
        limb_split(ti[x][i], h, l);
        outT[2 * (size_t)UTP + o] = h; outT[3 * (size_t)UTP + o] = l;
    }
}

// mode 2 fused (fold1 ∘ unfold2) + convert
__global__ void conv_m2(const float* __restrict__ sre, const float* __restrict__ sim,
                        __nv_bfloat16* __restrict__ outT, __nv_bfloat16* __restrict__ outU)
{
    __shared__ float tr[32][33], ti[32][33];
    const int z  = blockIdx.z;              // b*128 + i0
    const int b  = z >> 7, i0 = z & 127;
    const int r0 = blockIdx.y * 32;         // i1 tile
    const int c0 = blockIdx.x * 32;         // i2 tile
    const int x = threadIdx.x, y = threadIdx.y;
#pragma unroll
    for (int i = y; i < 32; i += 8) {
        size_t si = (((size_t)b * 128 + (r0 + i)) * 128 + i0) * 64 + c0 + x;
        float xr = sre[si], xi = sim[si];
        tr[i][x] = xr; ti[i][x] = xi;
        size_t o = ((size_t)b * 16384 + i0 * 128 + (r0 + i)) * 64 + c0 + x;
        __nv_bfloat16 h, l;
        limb_split(xr, h, l);
        outT[0 * (size_t)UTP + o] = h; outT[1 * (size_t)UTP + o] = l;
        limb_split(xi, h, l);
        outT[2 * (size_t)UTP + o] = h; outT[3 * (size_t)UTP + o] = l;
    }
    __syncthreads();
#pragma unroll
    for (int i = y; i < 32; i += 8) {
        size_t uo = ((size_t)b * 64 + c0 + i) * 16384 + i0 * 128 + r0 + x;
        __nv_bfloat16 h, l;
        limb_split(tr[x][i], h, l);
        outU[0 * (size_t)UTP + uo] = h; outU[1 * (size_t)UTP + uo] = l;
        limb_split(ti[x][i], h, l);
        outU[2 * (size_t)UTP + uo] = h; outU[3 * (size_t)UTP + uo] = l;
    }
}

// ================= mma.sync / cp.async helpers ============================
__device__ __forceinline__ unsigned smem_u32(const void* p) {
    unsigned a;
    asm("{ .reg .u64 t; cvta.to.shared.u64 t, %1; cvt.u32.u64 %0, t; }"
        : "=r"(a) : "l"(p));
    return a;
}
__device__ __forceinline__ void cpasync16(unsigned saddr, const void* g) {
    asm volatile("cp.async.cg.shared.global [%0], [%1], 16;" :: "r"(saddr), "l"(g));
}
#define CP_COMMIT() asm volatile("cp.async.commit_group;" ::: "memory")
#define CP_WAIT0()  asm volatile("cp.async.wait_group 0;" ::: "memory")
#define CP_WAIT1()  asm volatile("cp.async.wait_group 1;" ::: "memory")
__device__ __forceinline__ void ldm_x4(unsigned* r, unsigned addr) {
    asm volatile("ldmatrix.sync.aligned.m8n8.x4.shared.b16 {%0,%1,%2,%3}, [%4];"
                 : "=r"(r[0]), "=r"(r[1]), "=r"(r[2]), "=r"(r[3]) : "r"(addr));
}
__device__ __forceinline__ void mma16816(float* c, const unsigned* a, const unsigned* b) {
    asm volatile(
        "mma.sync.aligned.m16n8k16.row.col.f32.bf16.bf16.f32 "
        "{%0,%1,%2,%3}, {%4,%5,%6,%7}, {%8,%9}, {%0,%1,%2,%3};"
        : "+f"(c[0]), "+f"(c[1]), "+f"(c[2]), "+f"(c[3])
        : "r"(a[0]), "r"(a[1]), "r"(a[2]), "r"(a[3]), "r"(b[0]), "r"(b[1]));
}
__device__ __forceinline__ void wlimb2(__nv_bfloat16* out, size_t idx,
                                       float v0, float v1, int phi, int plo)
{
    __nv_bfloat16 h0, l0, h1, l1;
    limb_split(v0, h0, l0); limb_split(v1, h1, l1);
    unsigned hp = (unsigned)*(unsigned short*)&h0 | ((unsigned)*(unsigned short*)&h1 << 16);
    unsigned lp = (unsigned)*(unsigned short*)&l0 | ((unsigned)*(unsigned short*)&l1 << 16);
    *(unsigned*)(out + (size_t)phi * UTP + idx) = hp;
    *(unsigned*)(out + (size_t)plo * UTP + idx) = lp;
}

#define MMA12(pcr, pci, af, nih, nil_, brh, brl, bih, bil)                   \
    mma16816(pcr, af[0], brh); mma16816(pcr, af[0], brl);                    \
    mma16816(pcr, af[1], brh); mma16816(pcr, nih,   bih);                    \
    mma16816(pcr, nih,   bil); mma16816(pcr, nil_,  bih);                    \
    mma16816(pci, af[0], bih); mma16816(pci, af[0], bil);                    \
    mma16816(pci, af[1], bih); mma16816(pci, af[2], brh);                    \
    mma16816(pci, af[2], brl); mma16816(pci, af[3], brh);

// shared 64x128 compute body (As 4x64 rows, Bs 4x128 rows, APITCH pitch)
#define BODY_64x128(As, Bs)                                                    \
    for (int s = 0; s < 2; s++) {                                              \
        unsigned bf[4][2][4];                                                  \
        for (int p = 0; p < 4; p++)                                            \
            for (int gj = 0; gj < 2; gj++) {                                   \
                unsigned addr = smem_u32(Bs + p * BPL                          \
                    + (wn * 32 + gj * 16 + bro + l8) * APITCH + s * 16 + bko); \
                ldm_x4(bf[p][gj], addr);                                       \
            }                                                                  \
        for (int mi = 0; mi < 2; mi++) {                                       \
            unsigned af[4][4];                                                 \
            for (int p = 0; p < 4; p++) {                                      \
                unsigned addr = smem_u32(As + p * APL                          \
                    + (wm * 32 + mi * 16 + aro + l8) * APITCH + s * 16 + ako); \
                ldm_x4(af[p], addr);                                           \
            }                                                                  \
            unsigned nih[4], nil_[4];                                          \
            for (int q = 0; q < 4; q++) {                                      \
                nih[q]  = af[2][q] ^ 0x80008000u;                              \
                nil_[q] = af[3][q] ^ 0x80008000u;                              \
            }                                                                  \
            for (int ns = 0; ns < 4; ns++) {                                   \
                const unsigned* brh = &bf[0][ns >> 1][(ns & 1) * 2];           \
                const unsigned* brl = &bf[1][ns >> 1][(ns & 1) * 2];           \
                const unsigned* bih = &bf[2][ns >> 1][(ns & 1) * 2];           \
                const unsigned* bil = &bf[3][ns >> 1][(ns & 1) * 2];           \
                MMA12(cr[mi][ns], ci[mi][ns], af, nih, nil_, brh, brl, bih, bil) \
            }                                                                  \
        }                                                                      \
    }

// ================= tensor NN: C[b] = A(b?) * U[b] =========================
// 3-stage cp.async pipeline; CTA 64x128, 8 warps (2m x 4n)
#define APITCH 40
#define APL (64 * APITCH)
#define BPL (128 * APITCH)
#define NNBUF (4 * APL + 4 * BPL)
#define SMEM_TN (3 * NNBUF * 2)             // 184320 bytes

__global__ void __launch_bounds__(256, 1)
tensor_nn(const __nv_bfloat16* __restrict__ Ab, int strideAb,
          const __nv_bfloat16* __restrict__ UTb,
          float* __restrict__ Cre, float* __restrict__ Cim,
          __nv_bfloat16* __restrict__ Lbf, int outmode,
          int d, int rest)
{
    extern __shared__ __align__(16) char smem[];
    __nv_bfloat16* bufs = (__nv_bfloat16*)smem;

    const int tid = threadIdx.x, lane = tid & 31, wid = tid >> 5;
    const int b = blockIdx.z, m0 = blockIdx.y * 64, n0 = blockIdx.x * 128;
    const int wm = wid >> 2, wn = wid & 3;

    const int rsel = lane >> 3, l8 = lane & 7;
    const int aro = (rsel & 1) ? 8 : 0, ako = (rsel & 2) ? 8 : 0;
    const int bko = (rsel & 1) ? 8 : 0, bro = (rsel & 2) ? 8 : 0;

    const size_t abase = (size_t)b * strideAb;
    const size_t bbase = (size_t)b * rest * d;

    float cr[2][4][4], ci[2][4][4];
#pragma unroll
    for (int mi = 0; mi < 2; mi++)
#pragma unroll
        for (int ns = 0; ns < 4; ns++)
#pragma unroll
            for (int q = 0; q < 4; q++) { cr[mi][ns][q] = 0.f; ci[mi][ns][q] = 0.f; }

    const int nchunks = d / 32;

#define NN_ISSUE(cc)                                                           \
    {                                                                          \
        __nv_bfloat16* As_ = bufs + ((cc) % 3) * NNBUF;                        \
        __nv_bfloat16* Bs_ = As_ + 4 * APL;                                    \
        for (int u = tid; u < 1024; u += 256) {                                \
            int p = u >> 8, v = u & 255;                                       \
            int r = v >> 2, j = v & 3;                                         \
            cpasync16(smem_u32(As_ + p * APL + r * APITCH + j * 8),            \
                      Ab + (size_t)p * ALP + abase + (size_t)(m0 + r) * d      \
                      + (cc) * 32 + j * 8);                                    \
        }                                                                      \
        for (int u = tid; u < 2048; u += 256) {                                \
            int p = u >> 9, v = u & 511;                                       \
            int r = v >> 2, j = v & 3;                                         \
            cpasync16(smem_u32(Bs_ + p * BPL + r * APITCH + j * 8),            \
                      UTb + (size_t)p * UTP + bbase + (size_t)(n0 + r) * d     \
                      + (cc) * 32 + j * 8);                                    \
        }                                                                      \
        CP_COMMIT();                                                           \
    }

    NN_ISSUE(0)
    if (nchunks > 1) NN_ISSUE(1)
    for (int c = 0; c < nchunks; c++) {
        if (c + 1 < nchunks) CP_WAIT1(); else CP_WAIT0();
        __syncthreads();
        if (c + 2 < nchunks) NN_ISSUE(c + 2)

        __nv_bfloat16* As = bufs + (c % 3) * NNBUF;
        __nv_bfloat16* Bs = As + 4 * APL;
#pragma unroll
        BODY_64x128(As, Bs)
        __syncthreads();
    }

    const int g = lane >> 2, t = lane & 3;
    const size_t base = (size_t)b * d * rest;
#pragma unroll
    for (int mi = 0; mi < 2; mi++) {
        int mrow = m0 + wm * 32 + mi * 16 + g;
#pragma unroll
        for (int ns = 0; ns < 4; ns++) {
            int col = n0 + wn * 32 + ns * 8 + 2 * t;
            if (outmode == 0) {
                *(float2*)(Cre + base + (size_t)mrow * rest + col) =
                    make_float2(cr[mi][ns][0], cr[mi][ns][1]);
                *(float2*)(Cre + base + (size_t)(mrow + 8) * rest + col) =
                    make_float2(cr[mi][ns][2], cr[mi][ns][3]);
                *(float2*)(Cim + base + (size_t)mrow * rest + col) =
                    make_float2(ci[mi][ns][0], ci[mi][ns][1]);
                *(float2*)(Cim + base + (size_t)(mrow + 8) * rest + col) =
                    make_float2(ci[mi][ns][2], ci[mi][ns][3]);
            } else {
                size_t i0 = base + (size_t)mrow * rest + col;
                size_t i1 = base + (size_t)(mrow + 8) * rest + col;
                wlimb2(Lbf, i0, cr[mi][ns][0], cr[mi][ns][1], 0, 1);
                wlimb2(Lbf, i1, cr[mi][ns][2], cr[mi][ns][3], 0, 1);
                wlimb2(Lbf, i0, ci[mi][ns][0], ci[mi][ns][1], 2, 3);
                wlimb2(Lbf, i1, ci[mi][ns][2], ci[mi][ns][3], 2, 3);
            }
        }
    }
}

// ============ tensor NT split-K: P[chunk][b] = L[b] * U[b]^T ==============
// CTA 64x64, 2-stage cp.async, 2 CTAs/SM (proven best shape)
#define NTPL (64 * APITCH)
#define NTBUF (8 * NTPL)
#define SMEM_NT (2 * NTBUF * 2)              // 81920 bytes

__global__ void __launch_bounds__(256, 2)
tensor_nt(const __nv_bfloat16* __restrict__ Lb, const __nv_bfloat16* __restrict__ Ub,
          float* __restrict__ Pre, float* __restrict__ Pim,
          int d, int K, int KC)
{
    extern __shared__ __align__(16) char smem[];
    __nv_bfloat16* buf[2] = { (__nv_bfloat16*)smem, (__nv_bfloat16*)smem + NTBUF };

    const int tid = threadIdx.x, lane = tid & 31, wid = tid >> 5;
    const int bz = blockIdx.z, b = bz & 7, chunk = bz >> 3;
    const int m0 = blockIdx.y * 64, n0 = blockIdx.x * 64;
    const int wm = wid >> 2, wn = wid & 3;

    const int rsel = lane >> 3, l8 = lane & 7;
    const int aro = (rsel & 1) ? 8 : 0, ako = (rsel & 2) ? 8 : 0;
    const int bko = (rsel & 1) ? 8 : 0, bro = (rsel & 2) ? 8 : 0;

    float cr[2][2][4], ci[2][2][4];
#pragma unroll
    for (int mi = 0; mi < 2; mi++)
#pragma unroll
        for (int ns = 0; ns < 2; ns++)
#pragma unroll
            for (int q = 0; q < 4; q++) { cr[mi][ns][q] = 0.f; ci[mi][ns][q] = 0.f; }

    const size_t bb = (size_t)b * d * K;
    const int kbeg = chunk * KC;
    const int nchunks = KC / 32;

#define NT_ISSUE(cc, bx)                                                       \
    {                                                                          \
        __nv_bfloat16* As_ = buf[bx];                                          \
        __nv_bfloat16* Bs_ = buf[bx] + 4 * NTPL;                               \
        const int ko = kbeg + (cc) * 32;                                       \
        for (int u = tid; u < 1024; u += 256) {                                \
            int p = u >> 8, v = u & 255;                                       \
            int r = v >> 2, j = v & 3;                                         \
            cpasync16(smem_u32(As_ + p * NTPL + r * APITCH + j * 8),           \
                      Lb + (size_t)p * UTP + bb + (size_t)(m0 + r) * K + ko + j * 8); \
            cpasync16(smem_u32(Bs_ + p * NTPL + r * APITCH + j * 8),           \
                      Ub + (size_t)p * UTP + bb + (size_t)(n0 + r) * K + ko + j * 8); \
        }                                                                      \
        CP_COMMIT();                                                           \
    }

    NT_ISSUE(0, 0)
    for (int c = 0; c < nchunks; c++) {
        CP_WAIT0();
        __syncthreads();
        if (c + 1 < nchunks) NT_ISSUE(c + 1, (c + 1) & 1)

        __nv_bfloat16* As = buf[c & 1];
        __nv_bfloat16* Bs = buf[c & 1] + 4 * NTPL;
#pragma unroll
        for (int s = 0; s < 2; s++) {
            unsigned bf[4][4];
#pragma unroll
            for (int p = 0; p < 4; p++) {
                unsigned addr = smem_u32(Bs + p * NTPL
                    + (wn * 16 + bro + l8) * APITCH + s * 16 + bko);
                ldm_x4(bf[p], addr);
            }
#pragma unroll
            for (int mi = 0; mi < 2; mi++) {
                unsigned af[4][4];
#pragma unroll
                for (int p = 0; p < 4; p++) {
                    unsigned addr = smem_u32(As + p * NTPL
                        + (wm * 32 + mi * 16 + aro + l8) * APITCH + s * 16 + ako);
                    ldm_x4(af[p], addr);
                }
                unsigned nih[4], nil_[4];
#pragma unroll
                for (int q = 0; q < 4; q++) {
                    nih[q]  = af[2][q] ^ 0x80008000u;
                    nil_[q] = af[3][q] ^ 0x80008000u;
                }
#pragma unroll
                for (int ns = 0; ns < 2; ns++) {
                    const unsigned* brh = &bf[0][ns * 2];
                    const unsigned* brl = &bf[1][ns * 2];
                    const unsigned* bih = &bf[2][ns * 2];
                    const unsigned* bil = &bf[3][ns * 2];
                    MMA12(cr[mi][ns], ci[mi][ns], af, nih, nil_, brh, brl, bih, bil)
                }
            }
        }
        __syncthreads();
    }

    const int g = lane >> 2, t = lane & 3;
    const size_t off = (size_t)(chunk * BATCH + b) * d * d;
#pragma unroll
    for (int mi = 0; mi < 2; mi++) {
        int mrow = m0 + wm * 32 + mi * 16 + g;
#pragma unroll
        for (int ns = 0; ns < 2; ns++) {
            int col = n0 + wn * 16 + ns * 8 + 2 * t;
            *(float2*)(Pre + off + (size_t)mrow * d + col) =
                make_float2(cr[mi][ns][0], cr[mi][ns][1]);
            *(float2*)(Pre + off + (size_t)(mrow + 8) * d + col) =
                make_float2(cr[mi][ns][2], cr[mi][ns][3]);
            *(float2*)(Pim + off + (size_t)mrow * d + col) =
                make_float2(ci[mi][ns][0], ci[mi][ns][1]);
            *(float2*)(Pim + off + (size_t)(mrow + 8) * d + col) =
                make_float2(ci[mi][ns][2], ci[mi][ns][3]);
        }
    }
}

// ---------------- fused split-K reduce + softmax(|s|/scale)*phase ---------
__global__ void softmax_fused(const float* __restrict__ Pre, const float* __restrict__ Pim,
                              float* __restrict__ Mre, float* __restrict__ Mim,
                              int d, int n, int nchunks,
                              const float* __restrict__ logtau, float sfac)
{
    const int row = blockIdx.x;
    const int j   = threadIdx.x;
    const int idx = row * d + j;

    float sr = 0.f, si = 0.f;
    for (int c = 0; c < nchunks; c++) {
        sr += Pre[(size_t)c * n + idx];
        si += Pim[(size_t)c * n + idx];
    }
    const float mag = sqrtf(sr * sr + si * si);

    const float tau   = fmaxf(expf(logtau[0]), 1e-8f);
    const float scale = tau * sfac;
    const float logit = mag / scale;

    __shared__ float wred[4];
    __shared__ float wsum[4];
    const int warp = j >> 5, lane = j & 31, nw = d >> 5;

    float v = logit;
#pragma unroll
    for (int o = 16; o > 0; o >>= 1) v = fmaxf(v, __shfl_xor_sync(0xffffffffu, v, o));
    if (lane == 0) wred[warp] = v;
    __syncthreads();
    float mx = wred[0];
    for (int w = 1; w < nw; w++) mx = fmaxf(mx, wred[w]);

    const float e = expf(logit - mx);
    float s_ = e;
#pragma unroll
    for (int o = 16; o > 0; o >>= 1) s_ += __shfl_xor_sync(0xffffffffu, s_, o);
    if (lane == 0) wsum[warp] = s_;
    __syncthreads();
    float tot = 0.f;
    for (int w = 0; w < nw; w++) tot += wsum[w];

    const float routing = e / tot;
    float pr, pi;
    if (mag > 1e-8f) { pr = sr / mag; pi = si / mag; }
    else             { pr = 1.f;      pi = 0.f; }
    Mre[(size_t)row * d + j] = routing * pr;
    Mim[(size_t)row * d + j] = routing * pi;
}

// ---------------- final fold transpose ------------------------------------
__global__ void perm_transpose(const float* __restrict__ sre, const float* __restrict__ sim,
                               float* __restrict__ dre, float* __restrict__ dim_,
                               int R, int C)
{
    __shared__ float tre[32][33], tim[32][33];
    const int b  = blockIdx.z;
    const int r0 = blockIdx.y * 32;
    const int c0 = blockIdx.x * 32;
    const float* sr_ = sre + (size_t)b * R * C;
    const float* si_ = sim + (size_t)b * R * C;
    float*       dr_ = dre + (size_t)b * R * C;
    float*       di_ = dim_ + (size_t)b * R * C;
    const int x = threadIdx.x, y = threadIdx.y;
#pragma unroll
    for (int i = y; i < 32; i += 8) {
        tre[i][x] = sr_[(size_t)(r0 + i) * C + c0 + x];
        tim[i][x] = si_[(size_t)(r0 + i) * C + c0 + x];
    }
    __syncthreads();
#pragma unroll
    for (int i = y; i < 32; i += 8) {
        dr_[(size_t)(c0 + i) * R + r0 + x] = tre[x][i];
        di_[(size_t)(c0 + i) * R + r0 + x] = tim[x][i];
    }
}

// --------------------------------------------------------------------------
extern "C" void kernel_launch(void* const* d_in, const int* in_sizes, int n_in,
                              void* d_out, int out_size)
{
    (void)in_sizes; (void)n_in; (void)out_size;
    const float* xre  = (const float*)d_in[0];
    const float* xim  = (const float*)d_in[1];
    const float* wre[3] = {(const float*)d_in[2], (const float*)d_in[4], (const float*)d_in[6]};
    const float* wim[3] = {(const float*)d_in[3], (const float*)d_in[5], (const float*)d_in[7]};
    const float* ltau = (const float*)d_in[8];
    float* out_re = (float*)d_out;
    float* out_im = out_re + (size_t)NTOT;

    float *s_re, *s_im, *l_re, *l_im, *p_re, *p_im, *m_re, *m_im;
    __nv_bfloat16 *abf, *utbf, *ubf, *lbf;
    cudaGetSymbolAddress((void**)&s_re,  g_s_re);
    cudaGetSymbolAddress((void**)&s_im,  g_s_im);
    cudaGetSymbolAddress((void**)&l_re,  g_l_re);
    cudaGetSymbolAddress((void**)&l_im,  g_l_im);
    cudaGetSymbolAddress((void**)&p_re,  g_p_re);
    cudaGetSymbolAddress((void**)&p_im,  g_p_im);
    cudaGetSymbolAddress((void**)&m_re,  g_m_re);
    cudaGetSymbolAddress((void**)&m_im,  g_m_im);
    cudaGetSymbolAddress((void**)&abf,   g_abf);
    cudaGetSymbolAddress((void**)&utbf,  g_utbf);
    cudaGetSymbolAddress((void**)&ubf,   g_ubf);
    cudaGetSymbolAddress((void**)&lbf,   g_lbf);

    cudaFuncSetAttribute(tensor_nn, cudaFuncAttributeMaxDynamicSharedMemorySize, SMEM_TN);
    cudaFuncSetAttribute(tensor_nt, cudaFuncAttributeMaxDynamicSharedMemorySize, SMEM_NT);

    for (int mode = 0; mode < 3; mode++) {
        const int d    = (mode < 2) ? 128 : 64;
        const int rest = SS / d;
        const float sfac = sqrtf((float)SS / (float)d);

        // ---- fused unfold + limb conversion ----
        if (mode == 0) {
            conv_ut<<<dim3(rest / 32, d / 32, BATCH), dim3(32, 8)>>>(xre, xim, utbf, ubf, d, rest);
        } else if (mode == 1) {
            conv_m1<<<dim3(2, 4, BATCH * 128), dim3(32, 8)>>>(s_re, s_im, utbf, ubf);
        } else {
            conv_m2<<<dim3(2, 4, BATCH * 128), dim3(32, 8)>>>(l_re, l_im, utbf, ubf);
        }
        conv_limbs_A<<<(d * d + 255) / 256, 256>>>(wre[mode], wim[mode], abf, d * d);

        // ---- NN1 (tensor): l = W * u  -> bf16 limb planes directly ----
        dim3 gnn(rest / 128, d / 64, BATCH);
        tensor_nn<<<gnn, 256, SMEM_TN>>>(abf, 0, utbf, l_re, l_im, lbf, 1, d, rest);

        // ---- NT (tensor split-K, 64x64 2 CTAs/SM): score partials ----
        const int NC = (mode < 2) ? 32 : 64;
        const int KC = rest / NC;               // 256
        dim3 g2(d / 64, d / 64, BATCH * NC);
        tensor_nt<<<g2, 256, SMEM_NT>>>(lbf, ubf, p_re, p_im, d, rest, KC);

        // ---- softmax + phase -> m ----
        const int n = BATCH * d * d;
        softmax_fused<<<BATCH * d, d>>>(p_re, p_im, m_re, m_im, d, n, NC, ltau, sfac);

        // ---- NN2 (tensor): mixed = m * u (fp32 out in mode-m layout) ----
        conv_limbs_A<<<(n + 255) / 256, 256>>>(m_re, m_im, abf, n);
        float* o_re = (mode == 0) ? s_re : l_re;
        float* o_im = (mode == 0) ? s_im : l_im;
        tensor_nn<<<gnn, 256, SMEM_TN>>>(abf, d * d, utbf, o_re, o_im, lbf, 0, d, rest);

        // ---- final fold (mode 2 only): out[b,p,k] = O2[b,k,p] ----
        if (mode == 2) {
            dim3 gt2(16384 / 32, 64 / 32, BATCH);
            perm_transpose<<<gt2, dim3(32, 8)>>>(l_re, l_im, out_re, out_im, 64, 16384);
        }
    }
}